// round 1
// baseline (speedup 1.0000x reference)
#include <cuda_runtime.h>
#include <cstddef>

// Problem constants
#define B_  2
#define T_  16
#define D_  64
#define H_  64
#define W_  64
#define BT_ 32           // B*T
#define HW_ 4096         // H*W
#define M_  131072       // BT*HW  (GEMM rows)
#define C2_ 128          // 2*D interleaved channels

// ---------------- scratch (device globals; no cudaMalloc allowed) --------------
__device__ float g_xnp [32*66*66*128];   // padded LN'd conv input (NHWC, interleaved ch)
__device__ float g_xc  [(size_t)M_*128]; // original x, (m, 2e+r) interleaved
__device__ float g_x2  [(size_t)M_*128]; // x + conv residual
__device__ float g_xeig[(size_t)M_*128];
__device__ float g_uout[(size_t)M_*128];
__device__ float g_dec [(size_t)M_*128];
__device__ float g_dn  [(size_t)M_*128];
__device__ float g_h1  [(size_t)M_*512];
__device__ float g_Wcp [9*128*128];
__device__ float g_WE  [128*128];
__device__ float g_WDec[128*128];
__device__ float g_W1p [128*512];
__device__ float g_W2p [512*128];
__device__ float g_bcp [128];
__device__ float g_b2p [128];
__device__ float g_gtp [128];
__device__ float g_btp [128];
__device__ float g_partial[32*16*128];
__device__ float g_xmean[32*128];
__device__ float g_od[2*BT_*64];
__device__ float g_cA[2*BT_*64];
__device__ float g_cB[2*BT_*64];

__device__ __forceinline__ float softplus_f(float x){
    return (x > 20.f) ? x : log1pf(expf(x));
}
__device__ __forceinline__ float gelu_f(float x){
    float x3 = x*x*x;
    return 0.5f*x*(1.f + tanhf(0.7978845608028654f*(x + 0.044715f*x3)));
}

// ---------------- prep: build permuted / complexified weights ------------------
__global__ void k_prep(const float* __restrict__ Wc, const float* __restrict__ bc,
                       const float* __restrict__ E_re, const float* __restrict__ E_im,
                       const float* __restrict__ Dec_re, const float* __restrict__ Dec_im,
                       const float* __restrict__ W1, const float* __restrict__ W2,
                       const float* __restrict__ b2, const float* __restrict__ g_t,
                       const float* __restrict__ b_t)
{
    int stride = gridDim.x*blockDim.x;
    int idx = blockIdx.x*blockDim.x + threadIdx.x;
    // Wcp[(p,icp,ocp)] = Wc[p][d+64r][e+64s], icp=2d+r, ocp=2e+s
    for (int i = idx; i < 9*128*128; i += stride){
        int ocp = i & 127, icp = (i>>7)&127, p = i>>14;
        int e = ocp>>1, s = ocp&1, d = icp>>1, r = icp&1;
        g_Wcp[i] = Wc[(p*128 + (d + 64*r))*128 + (e + 64*s)];
    }
    for (int i = idx; i < 128*128; i += stride){
        int cp = i & 127, rp = i>>7;
        int e = cp>>1, s = cp&1, d = rp>>1, r = rp&1;
        float ve, vd;
        if (s==0){ ve = (r==0)?  E_re[d*64+e]   : -E_im[d*64+e];
                   vd = (r==0)?  Dec_re[d*64+e] : -Dec_im[d*64+e]; }
        else     { ve = (r==0)?  E_im[d*64+e]   :  E_re[d*64+e];
                   vd = (r==0)?  Dec_im[d*64+e] :  Dec_re[d*64+e]; }
        g_WE[i] = ve; g_WDec[i] = vd;
    }
    for (int i = idx; i < 128*512; i += stride){
        int f = i & 511, rp = i>>9;
        int e = rp>>1, r = rp&1;
        g_W1p[i] = W1[(e + 64*r)*512 + f];
    }
    for (int i = idx; i < 512*128; i += stride){
        int cp = i & 127, f = i>>7;
        int e = cp>>1, s = cp&1;
        g_W2p[i] = W2[f*128 + (e + 64*s)];
    }
    for (int i = idx; i < 128; i += stride){
        int e = i>>1, r = i&1;
        g_bcp[i] = bc[e + 64*r];
        g_b2p[i] = b2[e + 64*r];
        g_gtp[i] = g_t[e + 64*r];
        g_btp[i] = b_t[e + 64*r];
    }
}

// ------------- LN over channels + transpose to pixel-major; fill conv pad -------
__global__ void k_ln(const float* __restrict__ x_re, const float* __restrict__ x_im,
                     const float* __restrict__ g_s, const float* __restrict__ b_s)
{
    int bt = blockIdx.x;   // 0..31
    int hy = blockIdx.y;   // 0..65
    if (hy >= 64){
        int row = (hy==64) ? 0 : 65;
        float* dst = &g_xnp[((size_t)(bt*66 + row)*66)*128];
        for (int i = threadIdx.x; i < 66*128; i += blockDim.x) dst[i] = 0.f;
        return;
    }
    int h = hy;
    __shared__ float sre[64][65], sim[64][65];
    __shared__ float smean[64], srs[64];
    const float* xr = x_re + (size_t)bt*64*4096 + h*64;
    const float* xi = x_im + (size_t)bt*64*4096 + h*64;
    for (int i = threadIdx.x; i < 4096; i += 256){
        int e = i>>6, w = i&63;
        sre[e][w] = xr[(size_t)e*4096 + w];
        sim[e][w] = xi[(size_t)e*4096 + w];
    }
    __syncthreads();
    int w = threadIdx.x>>2, part = threadIdx.x&3;
    float s = 0.f, s2 = 0.f;
    for (int e = part*16; e < part*16+16; e++){
        float a = sre[e][w], b = sim[e][w];
        s += a + b; s2 += a*a + b*b;
    }
    s  += __shfl_xor_sync(0xffffffffu, s, 1);  s2 += __shfl_xor_sync(0xffffffffu, s2, 1);
    s  += __shfl_xor_sync(0xffffffffu, s, 2);  s2 += __shfl_xor_sync(0xffffffffu, s2, 2);
    if (part == 0){
        float m = s*(1.f/128.f);
        float v = s2*(1.f/128.f) - m*m;
        smean[w] = m; srs[w] = rsqrtf(v + 1e-5f);
    }
    __syncthreads();
    float* xn  = &g_xnp[((size_t)(bt*66 + h+1)*66 + 1)*128];
    float* xcp = &g_xc [((size_t)(bt*64 + h)*64)*128];
    for (int i = threadIdx.x; i < 8192; i += 256){
        int w2 = i>>7, c = i&127;
        int e = c>>1, r = c&1;
        float raw = r ? sim[e][w2] : sre[e][w2];
        int cpos = e + 64*r;
        xn[w2*128 + c] = (raw - smean[w2])*srs[w2]*g_s[cpos] + b_s[cpos];
        xcp[i] = raw;
    }
    if (threadIdx.x < 128){
        g_xnp[((size_t)(bt*66 + h+1)*66 + 0 )*128 + threadIdx.x] = 0.f;
        g_xnp[((size_t)(bt*66 + h+1)*66 + 65)*128 + threadIdx.x] = 0.f;
    }
}

// ---------------- generic tiled SGEMM (BM=BN=128, BK=16, 8x8/thread) -----------
// MODE 0: conv implicit-im2col (A from g_xnp), out g_x2 = acc + bcp + g_xc
// MODE 1: g_xeig = g_x2 @ g_WE
// MODE 2: g_dec  = g_uout @ g_WDec
// MODE 3: g_h1   = gelu(g_dn @ g_W1p + b1)
// MODE 4: Cext  += g_h1 @ g_W2p + g_b2p
template<int MODE, int KK, int NN>
__global__ __launch_bounds__(256, 2) void k_gemm(float* __restrict__ Cext,
                                                 const float* __restrict__ biasExt)
{
    const float* A  = (MODE==1) ? g_x2 : (MODE==2) ? g_uout :
                      (MODE==3) ? g_dn : (MODE==4) ? g_h1 : (const float*)nullptr;
    const float* Bm = (MODE==0) ? g_Wcp : (MODE==1) ? g_WE :
                      (MODE==2) ? g_WDec : (MODE==3) ? g_W1p : g_W2p;
    float* Cm = (MODE==0) ? g_x2 : (MODE==1) ? g_xeig :
                (MODE==2) ? g_dec : (MODE==3) ? g_h1 : Cext;

    __shared__ float As[16][128];
    __shared__ float Bs[16][128];
    const int tid = threadIdx.x;
    const int bm = blockIdx.y, bn = blockIdx.x;
    const int ty = tid >> 4, tx = tid & 15;
    const int m0 = bm*128, n0 = bn*128;
    const int ar = tid >> 2, aq = tid & 3;
    const int br = tid >> 5, bcx = (tid & 31) << 2;

    float acc[8][8];
#pragma unroll
    for (int i = 0; i < 8; i++)
#pragma unroll
        for (int j = 0; j < 8; j++) acc[i][j] = 0.f;

    for (int k0 = 0; k0 < KK; k0 += 16){
        float4 a4[2];
        if (MODE == 0){
            int p  = k0 >> 7;         // ky*3+kx (BK=16 never straddles ic boundary)
            int ic0 = k0 & 127;
            int ky = p/3, kx = p - 3*ky;
#pragma unroll
            for (int rr = 0; rr < 2; rr++){
                int m = m0 + ar + rr*64;
                int bt = m >> 12, h = (m>>6)&63, w = m&63;
                const float* src = &g_xnp[(((size_t)(bt*66 + h + ky))*66 + (w + kx))*128
                                          + ic0 + aq*4];
                a4[rr] = *(const float4*)src;
            }
        } else {
#pragma unroll
            for (int rr = 0; rr < 2; rr++){
                int m = m0 + ar + rr*64;
                a4[rr] = *(const float4*)&A[(size_t)m*KK + k0 + aq*4];
            }
        }
#pragma unroll
        for (int rr = 0; rr < 2; rr++){
            As[aq*4+0][ar+rr*64] = a4[rr].x;
            As[aq*4+1][ar+rr*64] = a4[rr].y;
            As[aq*4+2][ar+rr*64] = a4[rr].z;
            As[aq*4+3][ar+rr*64] = a4[rr].w;
        }
#pragma unroll
        for (int rr = 0; rr < 2; rr++){
            int kr = k0 + br + rr*8;
            *(float4*)&Bs[br+rr*8][bcx] = *(const float4*)&Bm[(size_t)kr*NN + n0 + bcx];
        }
        __syncthreads();
#pragma unroll
        for (int k = 0; k < 16; k++){
            float a[8], b[8];
            *(float4*)&a[0] = *(float4*)&As[k][ty*8];
            *(float4*)&a[4] = *(float4*)&As[k][ty*8+4];
            *(float4*)&b[0] = *(float4*)&Bs[k][tx*8];
            *(float4*)&b[4] = *(float4*)&Bs[k][tx*8+4];
#pragma unroll
            for (int i = 0; i < 8; i++)
#pragma unroll
                for (int j = 0; j < 8; j++) acc[i][j] += a[i]*b[j];
        }
        __syncthreads();
    }
#pragma unroll
    for (int i = 0; i < 8; i++){
        int m = m0 + ty*8 + i;
#pragma unroll
        for (int j = 0; j < 8; j++){
            int c = n0 + tx*8 + j;
            size_t off = (size_t)m*NN + c;
            float v = acc[i][j];
            if (MODE == 0)      Cm[off] = v + g_bcp[c] + g_xc[off];
            else if (MODE == 1) Cm[off] = v;
            else if (MODE == 2) Cm[off] = v;
            else if (MODE == 3) Cm[off] = gelu_f(v + biasExt[c]);
            else                Cm[off] += v + g_b2p[c];
        }
    }
}

// ---------------- spatial mean of x_eig ----------------------------------------
__global__ void k_mean1()
{
    int bt = blockIdx.x, chunk = blockIdx.y;      // 32 x 16
    int c = threadIdx.x & 127, g = threadIdx.x >> 7;
    const float* src = &g_xeig[((size_t)bt*4096 + chunk*256)*128];
    float s = 0.f;
    for (int p = g; p < 256; p += 2) s += src[(size_t)p*128 + c];
    __shared__ float sb[2][128];
    sb[g][c] = s;
    __syncthreads();
    if (g == 0) g_partial[(bt*16 + chunk)*128 + c] = sb[0][c] + sb[1][c];
}
__global__ void k_mean2()
{
    int bt = blockIdx.x, c = threadIdx.x;
    float s = 0.f;
    for (int ch = 0; ch < 16; ch++) s += g_partial[(bt*16+ch)*128 + c];
    g_xmean[bt*128 + c] = s * (1.f/4096.f);
}

// ---------------- tiny sequential part: flux scan, source, gate, op coefs ------
__global__ void k_seq(const float* __restrict__ flux_re, const float* __restrict__ flux_im,
                      const float* __restrict__ dt_seq, const float* __restrict__ lam_flux_raw,
                      const float* __restrict__ Wsrc_re, const float* __restrict__ Wsrc_im,
                      const float* __restrict__ w_gate, const float* __restrict__ b_gate,
                      const float* __restrict__ lam_re_raw, const float* __restrict__ lam_im,
                      float* __restrict__ out3, int write_out3)
{
    __shared__ float fre[2][16][64], fim[2][16][64];
    int b = threadIdx.x >> 6, d = threadIdx.x & 63;
    float lamf = softplus_f(lam_flux_raw[d]);
    float vr = flux_re[b*64+d], vi = flux_im[b*64+d];
    for (int t = 0; t < 16; t++){
        float dt = dt_seq[b*16+t];
        float Af = expf(-lamf*dt);
        int bt = b*16 + t;
        float xr = g_xmean[bt*128 + 2*d], xi = g_xmean[bt*128 + 2*d + 1];
        vr = Af*vr + xr*dt;
        vi = Af*vi + xi*dt;
        fre[b][t][d] = vr; fim[b][t][d] = vi;
    }
    __syncthreads();
    int e = d;
    float lr = -softplus_f(lam_re_raw[e]);
    float li = lam_im[e];
    float inv = 1.f/(lr*lr + li*li);
    float wg = w_gate[e], bg = b_gate[e];
    for (int t = 0; t < 16; t++){
        float sr = 0.f, si = 0.f;
        for (int dd = 0; dd < 64; dd++){
            float wr = Wsrc_re[dd*64+e], wi = Wsrc_im[dd*64+e];
            float fr = fre[b][t][dd], fi = fim[b][t][dd];
            sr += fr*wr - fi*wi;
            si += fr*wi + fi*wr;
        }
        float gate = 1.f/(1.f + expf(-(fre[b][t][e]*wg + bg)));
        float dt = dt_seq[b*16+t];
        float er = expf(lr*dt);
        float odr = er*cosf(li*dt), odi = er*sinf(li*dt);
        float nr = odr - 1.f, ni = odi;
        float ofr = (nr*lr + ni*li)*inv;
        float ofi = (ni*lr - nr*li)*inv;
        int idx = (b*16+t)*64 + e;
        g_od[2*idx] = odr;        g_od[2*idx+1] = odi;
        g_cA[2*idx] = gate*ofr;   g_cA[2*idx+1] = gate*ofi;
        float s1r = sr*(1.f-gate), s1i = si*(1.f-gate);
        g_cB[2*idx]   = s1r*ofr - s1i*ofi;
        g_cB[2*idx+1] = s1r*ofi + s1i*ofr;
    }
    if (write_out3){
        out3[(b*64+e)*2+0] = fre[b][15][e];
        out3[(b*64+e)*2+1] = fim[b][15][e];
    }
}

// ---------------- per-(b,h,w,e) recurrence over T -------------------------------
__global__ void k_scan(const float* __restrict__ h_re, const float* __restrict__ h_im,
                       float* __restrict__ out2, int write_out2)
{
    int bh = blockIdx.x;                 // 0..127
    int b = bh >> 6, h = bh & 63;
    int w = (blockIdx.y << 2) + (threadIdx.x >> 6);
    int e = threadIdx.x & 63;
    __shared__ float s_od[16][128], s_cA[16][128], s_cB[16][128];
    for (int i = threadIdx.x; i < 16*128; i += 256){
        int t = i>>7, c = i&127;
        s_od[t][c] = g_od[b*2048 + i];
        s_cA[t][c] = g_cA[b*2048 + i];
        s_cB[t][c] = g_cB[b*2048 + i];
    }
    __syncthreads();
    int hw = h*64 + w;
    size_t hidx = ((size_t)(b*64 + h)*64 + w)*64 + e;
    float vr = h_re[hidx], vi = h_im[hidx];
    for (int t = 0; t < 16; t++){
        size_t xoff = (((size_t)(b*16+t)*4096 + hw)*64 + e)*2;
        float xr = g_xeig[xoff], xi = g_xeig[xoff+1];
        float odr = s_od[t][2*e], odi = s_od[t][2*e+1];
        float car = s_cA[t][2*e], cai = s_cA[t][2*e+1];
        float cbr = s_cB[t][2*e], cbi = s_cB[t][2*e+1];
        float ur = xr*car - xi*cai + cbr;
        float ui = xr*cai + xi*car + cbi;
        float nvr = odr*vr - odi*vi + ur;
        float nvi = odr*vi + odi*vr + ui;
        vr = nvr; vi = nvi;
        g_uout[xoff]   = vr;
        g_uout[xoff+1] = vi;
    }
    if (write_out2){
        out2[hidx*2]   = vr;
        out2[hidx*2+1] = vi;
    }
}

// ---------------- z-partial + LayerNorm over decoded ----------------------------
__global__ void k_ln2(float* __restrict__ out1)
{
    int row = blockIdx.x*8 + (threadIdx.x>>5);
    int lane = threadIdx.x & 31;
    const float* dec = &g_dec[(size_t)row*128];
    float v[4];
    float s = 0.f, s2 = 0.f;
#pragma unroll
    for (int q = 0; q < 4; q++){
        v[q] = dec[lane + q*32];
        s += v[q]; s2 += v[q]*v[q];
    }
#pragma unroll
    for (int o = 16; o; o >>= 1){
        s  += __shfl_xor_sync(0xffffffffu, s, o);
        s2 += __shfl_xor_sync(0xffffffffu, s2, o);
    }
    float m = s*(1.f/128.f);
    float rs = rsqrtf(s2*(1.f/128.f) - m*m + 1e-5f);
    const float* x2p = &g_x2[(size_t)row*128];
    float* o1  = &out1[(size_t)row*128];
    float* dnp = &g_dn[(size_t)row*128];
#pragma unroll
    for (int q = 0; q < 4; q++){
        int c = lane + q*32;
        o1[c]  = x2p[c] + v[q];
        dnp[c] = (v[q] - m)*rs*g_gtp[c] + g_btp[c];
    }
}

// ---------------- launch ---------------------------------------------------------
extern "C" void kernel_launch(void* const* d_in, const int* in_sizes, int n_in,
                              void* d_out, int out_size)
{
    const float* x_re   = (const float*)d_in[0];
    const float* x_im   = (const float*)d_in[1];
    const float* h_re   = (const float*)d_in[2];
    const float* h_im   = (const float*)d_in[3];
    const float* flux_re= (const float*)d_in[4];
    const float* flux_im= (const float*)d_in[5];
    const float* dt_seq = (const float*)d_in[6];
    const float* g_s    = (const float*)d_in[7];
    const float* b_s    = (const float*)d_in[8];
    const float* Wc     = (const float*)d_in[9];
    const float* bc     = (const float*)d_in[10];
    const float* g_t    = (const float*)d_in[11];
    const float* b_t    = (const float*)d_in[12];
    const float* E_re   = (const float*)d_in[13];
    const float* E_im   = (const float*)d_in[14];
    const float* Dec_re = (const float*)d_in[15];
    const float* Dec_im = (const float*)d_in[16];
    const float* lam_flux_raw = (const float*)d_in[17];
    const float* Wsrc_re= (const float*)d_in[18];
    const float* Wsrc_im= (const float*)d_in[19];
    const float* w_gate = (const float*)d_in[20];
    const float* b_gate = (const float*)d_in[21];
    const float* lam_re_raw = (const float*)d_in[22];
    const float* lam_im = (const float*)d_in[23];
    const float* W1     = (const float*)d_in[24];
    const float* b1     = (const float*)d_in[25];
    const float* W2     = (const float*)d_in[26];
    const float* b2     = (const float*)d_in[27];

    float* out = (float*)d_out;
    const int Z_ELEMS  = 2*16*64*64*64*2;   // 16777216
    const int H_ELEMS  = 2*64*64*64*2;      // 1048576
    const int F_ELEMS  = 2*64*2;            // 256
    int full = (out_size >= Z_ELEMS + H_ELEMS + F_ELEMS) ? 1 : 0;
    float* out2 = out + Z_ELEMS;
    float* out3 = out + Z_ELEMS + H_ELEMS;

    k_prep<<<256,256>>>(Wc, bc, E_re, E_im, Dec_re, Dec_im, W1, W2, b2, g_t, b_t);
    k_ln<<<dim3(32,66),256>>>(x_re, x_im, g_s, b_s);
    k_gemm<0,1152,128><<<dim3(1,1024),256>>>(nullptr, nullptr);   // conv -> x2
    k_gemm<1, 128,128><<<dim3(1,1024),256>>>(nullptr, nullptr);   // x2 @ WE -> xeig
    k_mean1<<<dim3(32,16),256>>>();
    k_mean2<<<32,128>>>();
    k_seq<<<1,128>>>(flux_re, flux_im, dt_seq, lam_flux_raw, Wsrc_re, Wsrc_im,
                     w_gate, b_gate, lam_re_raw, lam_im, out3, full);
    k_scan<<<dim3(128,16),256>>>(h_re, h_im, out2, full);
    k_gemm<2, 128,128><<<dim3(1,1024),256>>>(nullptr, nullptr);   // uout @ WDec -> dec
    k_ln2<<<16384,256>>>(out);                                    // out = x2+dec ; dn = LN
    k_gemm<3, 128,512><<<dim3(4,1024),256>>>(nullptr, b1);        // h1 = gelu(dn@W1p+b1)
    k_gemm<4, 512,128><<<dim3(1,1024),256>>>(out, nullptr);       // out += h1@W2p + b2p
}

// round 3
// speedup vs baseline: 1.8108x; 1.8108x over previous
#include <cuda_runtime.h>
#include <cuda_bf16.h>
#include <cstdint>
#include <cstddef>

// Problem constants
#define B_  2
#define T_  16
#define D_  64
#define BT_ 32           // B*T
#define M_  131072       // BT*HW  (GEMM rows)

// ---------------- scratch (device globals; no cudaMalloc allowed) --------------
__device__ float g_xnp [32*66*66*128];   // padded LN'd conv input (NHWC, interleaved ch)
__device__ float g_xc  [(size_t)M_*128]; // original x, (m, 2e+r) interleaved
__device__ float g_x2  [(size_t)M_*128]; // x + conv residual
__device__ float g_xeig[(size_t)M_*128];
__device__ float g_uout[(size_t)M_*128];
__device__ float g_dec [(size_t)M_*128];
__device__ float g_dn  [(size_t)M_*128];
__device__ float g_h1  [(size_t)M_*512];

// bf16 weight "smem images": per 32-k chunk, per n-row: 128B = [hi 32 bf16 | lo 32 bf16],
// 16B-chunk XOR swizzle (chunk ^ (n&7)) baked in.
__device__ __align__(16) __nv_bfloat16 g_BcI[128*36*64];
__device__ __align__(16) __nv_bfloat16 g_BEI[128*4*64];
__device__ __align__(16) __nv_bfloat16 g_BDI[128*4*64];
__device__ __align__(16) __nv_bfloat16 g_B1I[512*4*64];
__device__ __align__(16) __nv_bfloat16 g_B2I[128*16*64];

__device__ float g_bcp [128];
__device__ float g_b2p [128];
__device__ float g_gtp [128];
__device__ float g_btp [128];
__device__ float g_partial[32*16*128];
__device__ float g_xmean[32*128];
__device__ float g_od[2*BT_*64];
__device__ float g_cA[2*BT_*64];
__device__ float g_cB[2*BT_*64];

__device__ __forceinline__ float softplus_f(float x){
    return (x > 20.f) ? x : log1pf(expf(x));
}
__device__ __forceinline__ float gelu_f(float x){
    float x3 = x*x*x;
    return 0.5f*x*(1.f + tanhf(0.7978845608028654f*(x + 0.044715f*x3)));
}
__device__ __forceinline__ uint32_t smem_u32(const void* p){
    return (uint32_t)__cvta_generic_to_shared(p);
}

#define LDX4(r0,r1,r2,r3,addr) \
    asm volatile("ldmatrix.sync.aligned.m8n8.x4.shared.b16 {%0,%1,%2,%3},[%4];" \
        : "=r"(r0),"=r"(r1),"=r"(r2),"=r"(r3) : "r"(addr))

#define MMA16816(c, a, b) \
    asm volatile("mma.sync.aligned.m16n8k16.row.col.f32.bf16.bf16.f32 " \
        "{%0,%1,%2,%3},{%4,%5,%6,%7},{%8,%9},{%0,%1,%2,%3};" \
        : "+f"((c)[0]),"+f"((c)[1]),"+f"((c)[2]),"+f"((c)[3]) \
        : "r"((a)[0]),"r"((a)[1]),"r"((a)[2]),"r"((a)[3]),"r"((b)[0]),"r"((b)[1]))

#define CP_ASYNC16(saddr, gptr) \
    asm volatile("cp.async.cg.shared.global [%0], [%1], 16;" \
        :: "r"(saddr), "l"((const void*)(gptr)) : "memory")
#define CP_COMMIT()  asm volatile("cp.async.commit_group;" ::: "memory")
#define CP_WAIT0()   asm volatile("cp.async.wait_group 0;" ::: "memory")

// write a weight value into image layout
__device__ __forceinline__ void img_put(__nv_bfloat16* img, int NCh, int n, int k, float v){
    int kc = k >> 5, kl = k & 31;
    int c  = kl >> 3;
    size_t base = ((size_t)n*NCh + kc)*64;
    __nv_bfloat16 h = __float2bfloat16(v);
    float rem = v - __bfloat162float(h);
    img[base + (((c  )^(n&7))<<3) + (kl&7)] = h;
    img[base + (((c+4)^(n&7))<<3) + (kl&7)] = __float2bfloat16(rem);
}

// ---------------- prep: build bf16-split weight images --------------------------
__global__ void k_prep(const float* __restrict__ Wc, const float* __restrict__ bc,
                       const float* __restrict__ E_re, const float* __restrict__ E_im,
                       const float* __restrict__ Dec_re, const float* __restrict__ Dec_im,
                       const float* __restrict__ W1, const float* __restrict__ W2,
                       const float* __restrict__ b2, const float* __restrict__ g_t,
                       const float* __restrict__ b_t)
{
    int stride = gridDim.x*blockDim.x;
    int idx = blockIdx.x*blockDim.x + threadIdx.x;
    // conv: n=2e+s (128), k = p*128 + 2d+r (1152)
    for (int i = idx; i < 128*1152; i += stride){
        int k = i % 1152, n = i / 1152;
        int p = k >> 7, icp = k & 127;
        int d = icp>>1, r = icp&1, e = n>>1, s = n&1;
        img_put(g_BcI, 36, n, k, Wc[(p*128 + (d + 64*r))*128 + (e + 64*s)]);
    }
    // E / Dec: n=2e+s, k=2d+r
    for (int i = idx; i < 128*128; i += stride){
        int k = i & 127, n = i >> 7;
        int e = n>>1, s = n&1, d = k>>1, r = k&1;
        float ve, vd;
        if (s==0){ ve = (r==0)?  E_re[d*64+e]   : -E_im[d*64+e];
                   vd = (r==0)?  Dec_re[d*64+e] : -Dec_im[d*64+e]; }
        else     { ve = (r==0)?  E_im[d*64+e]   :  E_re[d*64+e];
                   vd = (r==0)?  Dec_im[d*64+e] :  Dec_re[d*64+e]; }
        img_put(g_BEI, 4, n, k, ve);
        img_put(g_BDI, 4, n, k, vd);
    }
    // W1: n=f (512), k=2e+r (128)
    for (int i = idx; i < 512*128; i += stride){
        int k = i & 127, f = i >> 7;
        int e = k>>1, r = k&1;
        img_put(g_B1I, 4, f, k, W1[(e + 64*r)*512 + f]);
    }
    // W2: n=2e+s (128), k=f (512)
    for (int i = idx; i < 128*512; i += stride){
        int k = i & 511, n = i >> 9;
        int e = n>>1, s = n&1;
        img_put(g_B2I, 16, n, k, W2[k*128 + (e + 64*s)]);
    }
    for (int i = idx; i < 128; i += stride){
        int e = i>>1, r = i&1;
        g_bcp[i] = bc[e + 64*r];
        g_b2p[i] = b2[e + 64*r];
        g_gtp[i] = g_t[e + 64*r];
        g_btp[i] = b_t[e + 64*r];
    }
}

// ------------- LN over channels + transpose to pixel-major; fill conv pad -------
__global__ void k_ln(const float* __restrict__ x_re, const float* __restrict__ x_im,
                     const float* __restrict__ g_s, const float* __restrict__ b_s)
{
    int bt = blockIdx.x;   // 0..31
    int hy = blockIdx.y;   // 0..65
    if (hy >= 64){
        int row = (hy==64) ? 0 : 65;
        float* dst = &g_xnp[((size_t)(bt*66 + row)*66)*128];
        for (int i = threadIdx.x; i < 66*128; i += blockDim.x) dst[i] = 0.f;
        return;
    }
    int h = hy;
    __shared__ float sre[64][65], sim[64][65];
    __shared__ float smean[64], srs[64];
    const float* xr = x_re + (size_t)bt*64*4096 + h*64;
    const float* xi = x_im + (size_t)bt*64*4096 + h*64;
    for (int i = threadIdx.x; i < 4096; i += 256){
        int e = i>>6, w = i&63;
        sre[e][w] = xr[(size_t)e*4096 + w];
        sim[e][w] = xi[(size_t)e*4096 + w];
    }
    __syncthreads();
    int w = threadIdx.x>>2, part = threadIdx.x&3;
    float s = 0.f, s2 = 0.f;
    for (int e = part*16; e < part*16+16; e++){
        float a = sre[e][w], b = sim[e][w];
        s += a + b; s2 += a*a + b*b;
    }
    s  += __shfl_xor_sync(0xffffffffu, s, 1);  s2 += __shfl_xor_sync(0xffffffffu, s2, 1);
    s  += __shfl_xor_sync(0xffffffffu, s, 2);  s2 += __shfl_xor_sync(0xffffffffu, s2, 2);
    if (part == 0){
        float m = s*(1.f/128.f);
        float v = s2*(1.f/128.f) - m*m;
        smean[w] = m; srs[w] = rsqrtf(v + 1e-5f);
    }
    __syncthreads();
    float* xn  = &g_xnp[((size_t)(bt*66 + h+1)*66 + 1)*128];
    float* xcp = &g_xc [((size_t)(bt*64 + h)*64)*128];
    for (int i = threadIdx.x; i < 8192; i += 256){
        int w2 = i>>7, c = i&127;
        int e = c>>1, r = c&1;
        float raw = r ? sim[e][w2] : sre[e][w2];
        int cpos = e + 64*r;
        xn[w2*128 + c] = (raw - smean[w2])*srs[w2]*g_s[cpos] + b_s[cpos];
        xcp[i] = raw;
    }
    if (threadIdx.x < 128){
        g_xnp[((size_t)(bt*66 + h+1)*66 + 0 )*128 + threadIdx.x] = 0.f;
        g_xnp[((size_t)(bt*66 + h+1)*66 + 65)*128 + threadIdx.x] = 0.f;
    }
}

// ---------------- bf16-split tensor-core GEMM (mma.sync, BM=BN=128, BK=32) ------
// MODE 0: conv im2col (A from g_xnp) -> g_x2 = acc + bcp + g_xc
// MODE 1: g_xeig = g_x2 @ BE      MODE 2: g_dec = g_uout @ BD
// MODE 3: g_h1 = gelu(g_dn @ B1 + b1)      MODE 4: Cext += g_h1 @ B2 + b2p
template<int MODE, int KK, int NN>
__global__ __launch_bounds__(256) void k_mma(float* __restrict__ Cext,
                                             const float* __restrict__ biasExt)
{
    extern __shared__ char smc[];
    const int tid = threadIdx.x, lane = tid & 31, wid = tid >> 5;
    const int wm = wid & 1, wn = wid >> 1;       // warps: 2 (m) x 4 (n)
    const int m0 = blockIdx.y*128, n0 = blockIdx.x*128;
    const int NC = KK/32;

    const float* A = (MODE==1) ? g_x2 : (MODE==2) ? g_uout :
                     (MODE==3) ? g_dn : (MODE==4) ? g_h1 : (const float*)nullptr;
    const __nv_bfloat16* Bimg = (MODE==0) ? g_BcI : (MODE==1) ? g_BEI :
                                (MODE==2) ? g_BDI : (MODE==3) ? g_B1I : g_B2I;

    uint32_t sbase = smem_u32(smc);
    float acc[4][4][4];
#pragma unroll
    for (int i=0;i<4;i++)
#pragma unroll
        for (int j=0;j<4;j++)
#pragma unroll
            for (int q=0;q<4;q++) acc[i][j][q] = 0.f;

    // ---------------- stage loader ----------------
    auto load_stage = [&](int chnk, int s){
        uint32_t sA = sbase + (uint32_t)s*32768u;
        uint32_t sB = sA + 16384u;
        // B: 1024 x 16B cp.async, swizzle baked in image
#pragma unroll
        for (int q = 0; q < 4; q++){
            int idx = q*256 + tid;
            int r = idx >> 3, ch = idx & 7;
            const __nv_bfloat16* src = Bimg + ((size_t)(n0 + r)*NC + chnk)*64 + ch*8;
            CP_ASYNC16(sB + r*128 + ch*16, src);
        }
        // A: fp32 -> bf16 hi/lo split
        {
            int row = tid >> 1;
            int g0  = (tid & 1) * 2;           // 16B chunk pair {g0, g0+1}
            int k0  = chnk*32;
            const float* src;
            if (MODE == 0){
                int m = m0 + row;
                int bt = m >> 12, hh = (m>>6)&63, ww = m&63;
                int p = k0 >> 7; int ky = p/3, kx = p - 3*ky;
                src = &g_xnp[(((size_t)(bt*66 + hh + ky))*66 + (ww + kx))*128
                             + (k0 & 127) + g0*8];
            } else {
                src = &A[(size_t)(m0 + row)*KK + k0 + g0*8];
            }
            float4 f0 = ((const float4*)src)[0];
            float4 f1 = ((const float4*)src)[1];
            float4 f2 = ((const float4*)src)[2];
            float4 f3 = ((const float4*)src)[3];
            float fs[16] = {f0.x,f0.y,f0.z,f0.w, f1.x,f1.y,f1.z,f1.w,
                            f2.x,f2.y,f2.z,f2.w, f3.x,f3.y,f3.z,f3.w};
            uint32_t hi[8], lo[8];
#pragma unroll
            for (int j = 0; j < 8; j++){
                __nv_bfloat162 h2 = __floats2bfloat162_rn(fs[2*j], fs[2*j+1]);
                hi[j] = *(uint32_t*)&h2;
                float r0 = fs[2*j]   - __low2float(h2);
                float r1 = fs[2*j+1] - __high2float(h2);
                __nv_bfloat162 l2 = __floats2bfloat162_rn(r0, r1);
                lo[j] = *(uint32_t*)&l2;
            }
            uint32_t rb = sA + row*128;
            int sw = (row & 7);
            *(uint4*)(smc + (rb - sbase) + (((g0  )^sw)<<4)) = make_uint4(hi[0],hi[1],hi[2],hi[3]);
            *(uint4*)(smc + (rb - sbase) + (((g0+1)^sw)<<4)) = make_uint4(hi[4],hi[5],hi[6],hi[7]);
            *(uint4*)(smc + (rb - sbase) + (((g0+4)^sw)<<4)) = make_uint4(lo[0],lo[1],lo[2],lo[3]);
            *(uint4*)(smc + (rb - sbase) + (((g0+5)^sw)<<4)) = make_uint4(lo[4],lo[5],lo[6],lo[7]);
        }
        CP_COMMIT();
    };

    for (int chnk = 0; chnk < NC; chnk++){
        int s = chnk & 1;
        if (chnk == 0) load_stage(0, 0);
        CP_WAIT0();
        __syncthreads();
        if (chnk + 1 < NC) load_stage(chnk+1, s^1);

        uint32_t sA = sbase + (uint32_t)s*32768u;
        uint32_t sB = sA + 16384u;
        const int sel = lane >> 3, l7 = lane & 7;
#pragma unroll
        for (int h = 0; h < 2; h++){
            uint32_t ah[4][4], al[4][4];
#pragma unroll
            for (int mf = 0; mf < 4; mf++){
                int rowl = wm*64 + mf*16 + l7 + ((sel&1)<<3);
                int ch   = 2*h + ((sel>>1)&1);
                uint32_t ad = sA + rowl*128 + (((ch  )^(rowl&7))<<4);
                LDX4(ah[mf][0],ah[mf][1],ah[mf][2],ah[mf][3], ad);
                uint32_t ad2 = sA + rowl*128 + (((ch+4)^(rowl&7))<<4);
                LDX4(al[mf][0],al[mf][1],al[mf][2],al[mf][3], ad2);
            }
            uint32_t bh[4][2], bl[4][2];
#pragma unroll
            for (int q = 0; q < 2; q++){
                int rowl = wn*32 + q*16 + l7 + (((sel>>1)&1)<<3);
                int ch   = 2*h + (sel&1);
                uint32_t bd = sB + rowl*128 + (((ch  )^(rowl&7))<<4);
                LDX4(bh[2*q][0],bh[2*q][1],bh[2*q+1][0],bh[2*q+1][1], bd);
                uint32_t bd2 = sB + rowl*128 + (((ch+4)^(rowl&7))<<4);
                LDX4(bl[2*q][0],bl[2*q][1],bl[2*q+1][0],bl[2*q+1][1], bd2);
            }
#pragma unroll
            for (int mf = 0; mf < 4; mf++)
#pragma unroll
                for (int nf = 0; nf < 4; nf++){
                    MMA16816(acc[mf][nf], ah[mf], bh[nf]);
                    MMA16816(acc[mf][nf], ah[mf], bl[nf]);
                    MMA16816(acc[mf][nf], al[mf], bh[nf]);
                }
        }
        __syncthreads();
    }

    // ---------------- epilogue ----------------
#pragma unroll
    for (int mf = 0; mf < 4; mf++){
#pragma unroll
        for (int nf = 0; nf < 4; nf++){
            int row = m0 + wm*64 + mf*16 + (lane>>2);
            int col = n0 + wn*32 + nf*8 + (lane&3)*2;
#pragma unroll
            for (int half = 0; half < 2; half++){
                int r2 = row + half*8;
                float v0 = acc[mf][nf][half*2+0];
                float v1 = acc[mf][nf][half*2+1];
                size_t off = (size_t)r2*NN + col;
                if (MODE == 0){
                    float2 xc = *(const float2*)&g_xc[off];
                    float2 o = { v0 + g_bcp[col] + xc.x, v1 + g_bcp[col+1] + xc.y };
                    *(float2*)&g_x2[off] = o;
                } else if (MODE == 1){
                    float2 o = { v0, v1 };
                    *(float2*)&g_xeig[off] = o;
                } else if (MODE == 2){
                    float2 o = { v0, v1 };
                    *(float2*)&g_dec[off] = o;
                } else if (MODE == 3){
                    float2 o = { gelu_f(v0 + biasExt[col]), gelu_f(v1 + biasExt[col+1]) };
                    *(float2*)&g_h1[off] = o;
                } else {
                    float2 p = *(const float2*)&Cext[off];
                    float2 o = { p.x + v0 + g_b2p[col], p.y + v1 + g_b2p[col+1] };
                    *(float2*)&Cext[off] = o;
                }
            }
        }
    }
}

// ---------------- spatial mean of x_eig ----------------------------------------
__global__ void k_mean1()
{
    int bt = blockIdx.x, chunk = blockIdx.y;      // 32 x 16
    int c = threadIdx.x & 127, g = threadIdx.x >> 7;
    const float* src = &g_xeig[((size_t)bt*4096 + chunk*256)*128];
    float s = 0.f;
    for (int p = g; p < 256; p += 2) s += src[(size_t)p*128 + c];
    __shared__ float sb[2][128];
    sb[g][c] = s;
    __syncthreads();
    if (g == 0) g_partial[(bt*16 + chunk)*128 + c] = sb[0][c] + sb[1][c];
}
__global__ void k_mean2()
{
    int bt = blockIdx.x, c = threadIdx.x;
    float s = 0.f;
    for (int ch = 0; ch < 16; ch++) s += g_partial[(bt*16+ch)*128 + c];
    g_xmean[bt*128 + c] = s * (1.f/4096.f);
}

// ---------------- tiny sequential part ------------------------------------------
__global__ void k_seq(const float* __restrict__ flux_re, const float* __restrict__ flux_im,
                      const float* __restrict__ dt_seq, const float* __restrict__ lam_flux_raw,
                      const float* __restrict__ Wsrc_re, const float* __restrict__ Wsrc_im,
                      const float* __restrict__ w_gate, const float* __restrict__ b_gate,
                      const float* __restrict__ lam_re_raw, const float* __restrict__ lam_im,
                      float* __restrict__ out3, int write_out3)
{
    __shared__ float fre[2][16][64], fim[2][16][64];
    int b = threadIdx.x >> 6, d = threadIdx.x & 63;
    float lamf = softplus_f(lam_flux_raw[d]);
    float vr = flux_re[b*64+d], vi = flux_im[b*64+d];
    for (int t = 0; t < 16; t++){
        float dt = dt_seq[b*16+t];
        float Af = expf(-lamf*dt);
        int bt = b*16 + t;
        float xr = g_xmean[bt*128 + 2*d], xi = g_xmean[bt*128 + 2*d + 1];
        vr = Af*vr + xr*dt;
        vi = Af*vi + xi*dt;
        fre[b][t][d] = vr; fim[b][t][d] = vi;
    }
    __syncthreads();
    int e = d;
    float lr = -softplus_f(lam_re_raw[e]);
    float li = lam_im[e];
    float inv = 1.f/(lr*lr + li*li);
    float wg = w_gate[e], bg = b_gate[e];
    for (int t = 0; t < 16; t++){
        float sr = 0.f, si = 0.f;
        for (int dd = 0; dd < 64; dd++){
            float wr = Wsrc_re[dd*64+e], wi = Wsrc_im[dd*64+e];
            float fr = fre[b][t][dd], fi = fim[b][t][dd];
            sr += fr*wr - fi*wi;
            si += fr*wi + fi*wr;
        }
        float gate = 1.f/(1.f + expf(-(fre[b][t][e]*wg + bg)));
        float dt = dt_seq[b*16+t];
        float er = expf(lr*dt);
        float odr = er*cosf(li*dt), odi = er*sinf(li*dt);
        float nr = odr - 1.f, ni = odi;
        float ofr = (nr*lr + ni*li)*inv;
        float ofi = (ni*lr - nr*li)*inv;
        int idx = (b*16+t)*64 + e;
        g_od[2*idx] = odr;        g_od[2*idx+1] = odi;
        g_cA[2*idx] = gate*ofr;   g_cA[2*idx+1] = gate*ofi;
        float s1r = sr*(1.f-gate), s1i = si*(1.f-gate);
        g_cB[2*idx]   = s1r*ofr - s1i*ofi;
        g_cB[2*idx+1] = s1r*ofi + s1i*ofr;
    }
    if (write_out3){
        out3[(b*64+e)*2+0] = fre[b][15][e];
        out3[(b*64+e)*2+1] = fim[b][15][e];
    }
}

// ---------------- per-(b,h,w,e) recurrence over T -------------------------------
__global__ void k_scan(const float* __restrict__ h_re, const float* __restrict__ h_im,
                       float* __restrict__ out2, int write_out2)
{
    int bh = blockIdx.x;                 // 0..127
    int b = bh >> 6, h = bh & 63;
    int w = (blockIdx.y << 2) + (threadIdx.x >> 6);
    int e = threadIdx.x & 63;
    __shared__ float s_od[16][128], s_cA[16][128], s_cB[16][128];
    for (int i = threadIdx.x; i < 16*128; i += 256){
        int t = i>>7, c = i&127;
        s_od[t][c] = g_od[b*2048 + i];
        s_cA[t][c] = g_cA[b*2048 + i];
        s_cB[t][c] = g_cB[b*2048 + i];
    }
    __syncthreads();
    int hw = h*64 + w;
    size_t hidx = ((size_t)(b*64 + h)*64 + w)*64 + e;
    float vr = h_re[hidx], vi = h_im[hidx];
    for (int t = 0; t < 16; t++){
        size_t xoff = (((size_t)(b*16+t)*4096 + hw)*64 + e)*2;
        float xr = g_xeig[xoff], xi = g_xeig[xoff+1];
        float odr = s_od[t][2*e], odi = s_od[t][2*e+1];
        float car = s_cA[t][2*e], cai = s_cA[t][2*e+1];
        float cbr = s_cB[t][2*e], cbi = s_cB[t][2*e+1];
        float ur = xr*car - xi*cai + cbr;
        float ui = xr*cai + xi*car + cbi;
        float nvr = odr*vr - odi*vi + ur;
        float nvi = odr*vi + odi*vr + ui;
        vr = nvr; vi = nvi;
        g_uout[xoff]   = vr;
        g_uout[xoff+1] = vi;
    }
    if (write_out2){
        out2[hidx*2]   = vr;
        out2[hidx*2+1] = vi;
    }
}

// ---------------- z-partial + LayerNorm over decoded ----------------------------
__global__ void k_ln2(float* __restrict__ out1)
{
    int row = blockIdx.x*8 + (threadIdx.x>>5);
    int lane = threadIdx.x & 31;
    const float* dec = &g_dec[(size_t)row*128];
    float v[4];
    float s = 0.f, s2 = 0.f;
#pragma unroll
    for (int q = 0; q < 4; q++){
        v[q] = dec[lane + q*32];
        s += v[q]; s2 += v[q]*v[q];
    }
#pragma unroll
    for (int o = 16; o; o >>= 1){
        s  += __shfl_xor_sync(0xffffffffu, s, o);
        s2 += __shfl_xor_sync(0xffffffffu, s2, o);
    }
    float m = s*(1.f/128.f);
    float rs = rsqrtf(s2*(1.f/128.f) - m*m + 1e-5f);
    const float* x2p = &g_x2[(size_t)row*128];
    float* o1  = &out1[(size_t)row*128];
    float* dnp = &g_dn[(size_t)row*128];
#pragma unroll
    for (int q = 0; q < 4; q++){
        int c = lane + q*32;
        o1[c]  = x2p[c] + v[q];
        dnp[c] = (v[q] - m)*rs*g_gtp[c] + g_btp[c];
    }
}

// ---------------- launch ---------------------------------------------------------
extern "C" void kernel_launch(void* const* d_in, const int* in_sizes, int n_in,
                              void* d_out, int out_size)
{
    const float* x_re   = (const float*)d_in[0];
    const float* x_im   = (const float*)d_in[1];
    const float* h_re   = (const float*)d_in[2];
    const float* h_im   = (const float*)d_in[3];
    const float* flux_re= (const float*)d_in[4];
    const float* flux_im= (const float*)d_in[5];
    const float* dt_seq = (const float*)d_in[6];
    const float* g_s    = (const float*)d_in[7];
    const float* b_s    = (const float*)d_in[8];
    const float* Wc     = (const float*)d_in[9];
    const float* bc     = (const float*)d_in[10];
    const float* g_t    = (const float*)d_in[11];
    const float* b_t    = (const float*)d_in[12];
    const float* E_re   = (const float*)d_in[13];
    const float* E_im   = (const float*)d_in[14];
    const float* Dec_re = (const float*)d_in[15];
    const float* Dec_im = (const float*)d_in[16];
    const float* lam_flux_raw = (const float*)d_in[17];
    const float* Wsrc_re= (const float*)d_in[18];
    const float* Wsrc_im= (const float*)d_in[19];
    const float* w_gate = (const float*)d_in[20];
    const float* b_gate = (const float*)d_in[21];
    const float* lam_re_raw = (const float*)d_in[22];
    const float* lam_im = (const float*)d_in[23];
    const float* W1     = (const float*)d_in[24];
    const float* b1     = (const float*)d_in[25];
    const float* W2     = (const float*)d_in[26];
    const float* b2     = (const float*)d_in[27];

    float* out = (float*)d_out;
    const int Z_ELEMS  = 2*16*64*64*64*2;   // 16777216
    const int H_ELEMS  = 2*64*64*64*2;      // 1048576
    const int F_ELEMS  = 2*64*2;            // 256
    int full = (out_size >= Z_ELEMS + H_ELEMS + F_ELEMS) ? 1 : 0;
    float* out2 = out + Z_ELEMS;
    float* out3 = out + Z_ELEMS + H_ELEMS;

    const int SMEMSZ = 2*32768;   // 2 stages x (16KB A + 16KB B)
    cudaFuncSetAttribute(k_mma<0,1152,128>, cudaFuncAttributeMaxDynamicSharedMemorySize, SMEMSZ);
    cudaFuncSetAttribute(k_mma<1, 128,128>, cudaFuncAttributeMaxDynamicSharedMemorySize, SMEMSZ);
    cudaFuncSetAttribute(k_mma<2, 128,128>, cudaFuncAttributeMaxDynamicSharedMemorySize, SMEMSZ);
    cudaFuncSetAttribute(k_mma<3, 128,512>, cudaFuncAttributeMaxDynamicSharedMemorySize, SMEMSZ);
    cudaFuncSetAttribute(k_mma<4, 512,128>, cudaFuncAttributeMaxDynamicSharedMemorySize, SMEMSZ);

    k_prep<<<256,256>>>(Wc, bc, E_re, E_im, Dec_re, Dec_im, W1, W2, b2, g_t, b_t);
    k_ln<<<dim3(32,66),256>>>(x_re, x_im, g_s, b_s);
    k_mma<0,1152,128><<<dim3(1,1024),256,SMEMSZ>>>(nullptr, nullptr);   // conv -> x2
    k_mma<1, 128,128><<<dim3(1,1024),256,SMEMSZ>>>(nullptr, nullptr);   // x2 @ E -> xeig
    k_mean1<<<dim3(32,16),256>>>();
    k_mean2<<<32,128>>>();
    k_seq<<<1,128>>>(flux_re, flux_im, dt_seq, lam_flux_raw, Wsrc_re, Wsrc_im,
                     w_gate, b_gate, lam_re_raw, lam_im, out3, full);
    k_scan<<<dim3(128,16),256>>>(h_re, h_im, out2, full);
    k_mma<2, 128,128><<<dim3(1,1024),256,SMEMSZ>>>(nullptr, nullptr);   // uout @ Dec -> dec
    k_ln2<<<16384,256>>>(out);                                          // out = x2+dec ; dn = LN
    k_mma<3, 128,512><<<dim3(4,1024),256,SMEMSZ>>>(nullptr, b1);        // h1 = gelu(dn@W1+b1)
    k_mma<4, 512,128><<<dim3(1,1024),256,SMEMSZ>>>(out, nullptr);       // out += h1@W2 + b2
}

// round 5
// speedup vs baseline: 2.6014x; 1.4366x over previous
#include <cuda_runtime.h>
#include <cuda_bf16.h>
#include <cstdint>
#include <cstddef>

#define B_  2
#define T_  16
#define D_  64
#define BT_ 32
#define M_  131072

// ---------------- scratch (device globals) --------------------------------------
__device__ __align__(16) __nv_bfloat16 g_xnph[32*66*66*128], g_xnpl[32*66*66*128];
__device__ float g_xc  [(size_t)M_*128];
__device__ float g_x2  [(size_t)M_*128];
__device__ __align__(16) __nv_bfloat16 g_x2h[(size_t)M_*128], g_x2l[(size_t)M_*128];
__device__ float g_xeig[(size_t)M_*128];
__device__ __align__(16) __nv_bfloat16 g_uouth[(size_t)M_*128], g_uoutl[(size_t)M_*128];
__device__ __align__(16) __nv_bfloat16 g_dnh[(size_t)M_*128],  g_dnl[(size_t)M_*128];
__device__ __align__(16) __nv_bfloat16 g_h1h[(size_t)M_*512],  g_h1l[(size_t)M_*512];

// bf16 weight smem-images: per 32-k chunk per n-row: 128B = [hi 32 | lo 32] bf16,
// 16B-chunk XOR swizzle (chunk ^ (n&7)) baked in.
__device__ __align__(16) __nv_bfloat16 g_BcI[128*36*64];
__device__ __align__(16) __nv_bfloat16 g_BEI[128*4*64];
__device__ __align__(16) __nv_bfloat16 g_BDI[128*4*64];
__device__ __align__(16) __nv_bfloat16 g_B1I[512*4*64];
__device__ __align__(16) __nv_bfloat16 g_B2I[128*16*64];

__device__ float g_bcp [128];
__device__ float g_b2p [128];
__device__ float g_gtp [128];
__device__ float g_btp [128];
__device__ float g_partial[1024*128];
__device__ float g_xmean[32*128];
__device__ float g_od[2*BT_*64];
__device__ float g_cA[2*BT_*64];
__device__ float g_cB[2*BT_*64];

__device__ __forceinline__ float softplus_f(float x){
    return (x > 20.f) ? x : log1pf(expf(x));
}
__device__ __forceinline__ float gelu_f(float x){
    float x3 = x*x*x;
    return 0.5f*x*(1.f + tanhf(0.7978845608028654f*(x + 0.044715f*x3)));
}
__device__ __forceinline__ uint32_t smem_u32(const void* p){
    return (uint32_t)__cvta_generic_to_shared(p);
}
__device__ __forceinline__ void split2(float v0, float v1, uint32_t& hi, uint32_t& lo){
    __nv_bfloat16 h0 = __float2bfloat16(v0), h1 = __float2bfloat16(v1);
    __nv_bfloat16 l0 = __float2bfloat16(v0 - __bfloat162float(h0));
    __nv_bfloat16 l1 = __float2bfloat16(v1 - __bfloat162float(h1));
    __nv_bfloat162 hh; hh.x = h0; hh.y = h1; hi = *(uint32_t*)&hh;
    __nv_bfloat162 ll; ll.x = l0; ll.y = l1; lo = *(uint32_t*)&ll;
}

#define LDX4(r0,r1,r2,r3,addr) \
    asm volatile("ldmatrix.sync.aligned.m8n8.x4.shared.b16 {%0,%1,%2,%3},[%4];" \
        : "=r"(r0),"=r"(r1),"=r"(r2),"=r"(r3) : "r"(addr))
#define MMA16816(c, a, b) \
    asm volatile("mma.sync.aligned.m16n8k16.row.col.f32.bf16.bf16.f32 " \
        "{%0,%1,%2,%3},{%4,%5,%6,%7},{%8,%9},{%0,%1,%2,%3};" \
        : "+f"((c)[0]),"+f"((c)[1]),"+f"((c)[2]),"+f"((c)[3]) \
        : "r"((a)[0]),"r"((a)[1]),"r"((a)[2]),"r"((a)[3]),"r"((b)[0]),"r"((b)[1]))
#define CP_ASYNC16(saddr, gptr) \
    asm volatile("cp.async.cg.shared.global [%0], [%1], 16;" \
        :: "r"(saddr), "l"((const void*)(gptr)) : "memory")
#define CP_COMMIT()  asm volatile("cp.async.commit_group;" ::: "memory")
#define CP_WAIT0()   asm volatile("cp.async.wait_group 0;" ::: "memory")
#define CP_WAIT1()   asm volatile("cp.async.wait_group 1;" ::: "memory")

__device__ __forceinline__ void img_put(__nv_bfloat16* img, int NCh, int n, int k, float v){
    int kc = k >> 5, kl = k & 31;
    int c  = kl >> 3;
    size_t base = ((size_t)n*NCh + kc)*64;
    __nv_bfloat16 h = __float2bfloat16(v);
    float rem = v - __bfloat162float(h);
    img[base + (((c  )^(n&7))<<3) + (kl&7)] = h;
    img[base + (((c+4)^(n&7))<<3) + (kl&7)] = __float2bfloat16(rem);
}

// ---------------- prep ----------------------------------------------------------
__global__ void k_prep(const float* __restrict__ Wc, const float* __restrict__ bc,
                       const float* __restrict__ E_re, const float* __restrict__ E_im,
                       const float* __restrict__ Dec_re, const float* __restrict__ Dec_im,
                       const float* __restrict__ W1, const float* __restrict__ W2,
                       const float* __restrict__ b2, const float* __restrict__ g_t,
                       const float* __restrict__ b_t)
{
    int stride = gridDim.x*blockDim.x;
    int idx = blockIdx.x*blockDim.x + threadIdx.x;
    for (int i = idx; i < 128*1152; i += stride){
        int k = i % 1152, n = i / 1152;
        int p = k >> 7, icp = k & 127;
        int d = icp>>1, r = icp&1, e = n>>1, s = n&1;
        img_put(g_BcI, 36, n, k, Wc[(p*128 + (d + 64*r))*128 + (e + 64*s)]);
    }
    for (int i = idx; i < 128*128; i += stride){
        int k = i & 127, n = i >> 7;
        int e = n>>1, s = n&1, d = k>>1, r = k&1;
        float ve, vd;
        if (s==0){ ve = (r==0)?  E_re[d*64+e]   : -E_im[d*64+e];
                   vd = (r==0)?  Dec_re[d*64+e] : -Dec_im[d*64+e]; }
        else     { ve = (r==0)?  E_im[d*64+e]   :  E_re[d*64+e];
                   vd = (r==0)?  Dec_im[d*64+e] :  Dec_re[d*64+e]; }
        img_put(g_BEI, 4, n, k, ve);
        img_put(g_BDI, 4, n, k, vd);
    }
    for (int i = idx; i < 512*128; i += stride){
        int k = i & 127, f = i >> 7;
        int e = k>>1, r = k&1;
        img_put(g_B1I, 4, f, k, W1[(e + 64*r)*512 + f]);
    }
    for (int i = idx; i < 128*512; i += stride){
        int k = i & 511, n = i >> 9;
        int e = n>>1, s = n&1;
        img_put(g_B2I, 16, n, k, W2[k*128 + (e + 64*s)]);
    }
    for (int i = idx; i < 128; i += stride){
        int e = i>>1, r = i&1;
        g_bcp[i] = bc[e + 64*r];
        g_b2p[i] = b2[e + 64*r];
        g_gtp[i] = g_t[e + 64*r];
        g_btp[i] = b_t[e + 64*r];
    }
}

// ------------- LN + transpose; writes bf16 split conv image + fp32 residual -----
__global__ void k_ln(const float* __restrict__ x_re, const float* __restrict__ x_im,
                     const float* __restrict__ g_s, const float* __restrict__ b_s)
{
    int bt = blockIdx.x;   // 0..31
    int hy = blockIdx.y;   // 0..65
    if (hy >= 64){
        int row = (hy==64) ? 0 : 65;
        size_t base = ((size_t)(bt*66 + row)*66)*128;
        for (int i = threadIdx.x; i < 66*128; i += blockDim.x){
            g_xnph[base + i] = __float2bfloat16(0.f);
            g_xnpl[base + i] = __float2bfloat16(0.f);
        }
        return;
    }
    int h = hy;
    __shared__ float sre[64][65], sim[64][65];
    __shared__ float smean[64], srs[64];
    const float* xr = x_re + (size_t)bt*64*4096 + h*64;
    const float* xi = x_im + (size_t)bt*64*4096 + h*64;
    for (int i = threadIdx.x; i < 4096; i += 256){
        int e = i>>6, w = i&63;
        sre[e][w] = xr[(size_t)e*4096 + w];
        sim[e][w] = xi[(size_t)e*4096 + w];
    }
    __syncthreads();
    int w = threadIdx.x>>2, part = threadIdx.x&3;
    float s = 0.f, s2 = 0.f;
    for (int e = part*16; e < part*16+16; e++){
        float a = sre[e][w], b = sim[e][w];
        s += a + b; s2 += a*a + b*b;
    }
    s  += __shfl_xor_sync(0xffffffffu, s, 1);  s2 += __shfl_xor_sync(0xffffffffu, s2, 1);
    s  += __shfl_xor_sync(0xffffffffu, s, 2);  s2 += __shfl_xor_sync(0xffffffffu, s2, 2);
    if (part == 0){
        float m = s*(1.f/128.f);
        float v = s2*(1.f/128.f) - m*m;
        smean[w] = m; srs[w] = rsqrtf(v + 1e-5f);
    }
    __syncthreads();
    size_t xnb = ((size_t)(bt*66 + h+1)*66 + 1)*128;
    float* xcp = &g_xc[((size_t)(bt*64 + h)*64)*128];
    for (int i = threadIdx.x; i < 4096; i += 256){
        int w2 = i>>6, e = i&63;
        int cp2 = e*2;
        float r0 = sre[e][w2], r1 = sim[e][w2];
        float mm = smean[w2], rr = srs[w2];
        float n0 = (r0 - mm)*rr*g_s[e]    + b_s[e];
        float n1 = (r1 - mm)*rr*g_s[e+64] + b_s[e+64];
        uint32_t hi, lo; split2(n0, n1, hi, lo);
        size_t off = xnb + (size_t)w2*128 + cp2;
        *(uint32_t*)&g_xnph[off] = hi;
        *(uint32_t*)&g_xnpl[off] = lo;
        float2 rc = { r0, r1 };
        *(float2*)&xcp[(size_t)w2*128 + cp2] = rc;
    }
    if (threadIdx.x < 128){
        size_t bL = ((size_t)(bt*66 + h+1)*66 + 0 )*128 + threadIdx.x;
        size_t bR = ((size_t)(bt*66 + h+1)*66 + 65)*128 + threadIdx.x;
        g_xnph[bL] = __float2bfloat16(0.f);  g_xnpl[bL] = __float2bfloat16(0.f);
        g_xnph[bR] = __float2bfloat16(0.f);  g_xnpl[bR] = __float2bfloat16(0.f);
    }
}

// ---------------- bf16-split tensor-core GEMM, cp.async 3-stage -----------------
// MODE 0: conv im2col -> g_x2 (+split planes)
// MODE 1: xeig = x2 @ E  (+ column partials for spatial mean)
// MODE 2: dec = uout @ Dec, fused: out1 = x2+dec; dn = LN(dec) split planes
// MODE 3: h1 = gelu(dn @ W1 + b1) split planes
// MODE 4: out += h1 @ W2 + b2p
template<int MODE, int KK, int NN>
__global__ __launch_bounds__(256, 2) void k_mma(float* __restrict__ Cext,
                                                const float* __restrict__ biasExt)
{
    extern __shared__ char smc[];
    const int tid = threadIdx.x, lane = tid & 31, wid = tid >> 5;
    const int wm = wid & 1, wn = wid >> 1;
    const int m0 = blockIdx.y*128, n0 = blockIdx.x*128;
    const int NC = KK/32;

    const __nv_bfloat16* Ah = (MODE==1) ? g_x2h : (MODE==2) ? g_uouth :
                              (MODE==3) ? g_dnh : (MODE==4) ? g_h1h : (const __nv_bfloat16*)nullptr;
    const __nv_bfloat16* Al = (MODE==1) ? g_x2l : (MODE==2) ? g_uoutl :
                              (MODE==3) ? g_dnl : (MODE==4) ? g_h1l : (const __nv_bfloat16*)nullptr;
    const __nv_bfloat16* Bimg = (MODE==0) ? g_BcI : (MODE==1) ? g_BEI :
                                (MODE==2) ? g_BDI : (MODE==3) ? g_B1I : g_B2I;

    uint32_t sbase = smem_u32(smc);
    float acc[4][4][4];
#pragma unroll
    for (int i=0;i<4;i++)
#pragma unroll
        for (int j=0;j<4;j++)
#pragma unroll
            for (int q=0;q<4;q++) acc[i][j][q] = 0.f;

    auto load_stage = [&](int chnk, int s){
        uint32_t sA = sbase + (uint32_t)s*32768u;
        uint32_t sB = sA + 16384u;
        int k0 = chnk*32;
#pragma unroll
        for (int q = 0; q < 4; q++){
            int ca = q*256 + tid;
            int r = ca >> 3, ch = ca & 7;
            const __nv_bfloat16* src;
            if (MODE == 0){
                int m = m0 + r;
                int bt = m >> 12, hh = (m>>6)&63, ww = m&63;
                int p = k0 >> 7; int ky = p/3, kx = p - 3*ky;
                const __nv_bfloat16* pl = (ch < 4) ? g_xnph : g_xnpl;
                src = &pl[(((size_t)(bt*66 + hh + ky))*66 + (ww + kx))*128
                          + (k0 & 127) + (ch&3)*8];
            } else {
                const __nv_bfloat16* pl = (ch < 4) ? Ah : Al;
                src = &pl[(size_t)(m0 + r)*KK + k0 + (ch&3)*8];
            }
            CP_ASYNC16(sA + r*128 + (((uint32_t)(ch ^ (r&7)))<<4), src);
        }
#pragma unroll
        for (int q = 0; q < 4; q++){
            int cb = q*256 + tid;
            int r = cb >> 3, ch = cb & 7;
            const __nv_bfloat16* src = Bimg + ((size_t)(n0 + r)*NC + chnk)*64 + ch*8;
            CP_ASYNC16(sB + r*128 + ch*16, src);   // swizzle already baked into image
        }
        CP_COMMIT();
    };

    load_stage(0, 0);
    if (NC > 1) load_stage(1, 1);

    for (int chnk = 0; chnk < NC; chnk++){
        int s = chnk % 3;
        if (chnk < NC-1) CP_WAIT1(); else CP_WAIT0();
        __syncthreads();
        if (chnk + 2 < NC) load_stage(chnk+2, (chnk+2)%3);

        uint32_t sA = sbase + (uint32_t)s*32768u;
        uint32_t sB = sA + 16384u;
        const int sel = lane >> 3, l7 = lane & 7;
#pragma unroll
        for (int h = 0; h < 2; h++){
            uint32_t ah[4][4], al[4][4];
#pragma unroll
            for (int mf = 0; mf < 4; mf++){
                int rowl = wm*64 + mf*16 + l7 + ((sel&1)<<3);
                int ch   = 2*h + ((sel>>1)&1);
                uint32_t ad = sA + rowl*128 + (((ch  )^(rowl&7))<<4);
                LDX4(ah[mf][0],ah[mf][1],ah[mf][2],ah[mf][3], ad);
                uint32_t ad2 = sA + rowl*128 + (((ch+4)^(rowl&7))<<4);
                LDX4(al[mf][0],al[mf][1],al[mf][2],al[mf][3], ad2);
            }
            uint32_t bh[4][2], bl[4][2];
#pragma unroll
            for (int q = 0; q < 2; q++){
                int rowl = wn*32 + q*16 + l7 + (((sel>>1)&1)<<3);
                int ch   = 2*h + (sel&1);
                uint32_t bd = sB + rowl*128 + (((ch  )^(rowl&7))<<4);
                LDX4(bh[2*q][0],bh[2*q][1],bh[2*q+1][0],bh[2*q+1][1], bd);
                uint32_t bd2 = sB + rowl*128 + (((ch+4)^(rowl&7))<<4);
                LDX4(bl[2*q][0],bl[2*q][1],bl[2*q+1][0],bl[2*q+1][1], bd2);
            }
#pragma unroll
            for (int mf = 0; mf < 4; mf++)
#pragma unroll
                for (int nf = 0; nf < 4; nf++){
                    MMA16816(acc[mf][nf], ah[mf], bh[nf]);
                    MMA16816(acc[mf][nf], ah[mf], bl[nf]);
                    MMA16816(acc[mf][nf], al[mf], bh[nf]);
                }
        }
        __syncthreads();
    }

    // ---------------- epilogues ----------------
    if (MODE == 2){
        // fused: out1 = x2 + dec ; dn = LN(dec)*g+b -> split planes
        float* prs = (float*)smc;            // [4][128]
        float* prq = prs + 512;
#pragma unroll
        for (int mf = 0; mf < 4; mf++)
#pragma unroll
            for (int half = 0; half < 2; half++){
                float s = 0.f, q = 0.f;
#pragma unroll
                for (int nf = 0; nf < 4; nf++)
#pragma unroll
                    for (int j = 0; j < 2; j++){
                        float v = acc[mf][nf][half*2+j];
                        s += v; q += v*v;
                    }
                s += __shfl_xor_sync(0xffffffffu, s, 1);
                s += __shfl_xor_sync(0xffffffffu, s, 2);
                q += __shfl_xor_sync(0xffffffffu, q, 1);
                q += __shfl_xor_sync(0xffffffffu, q, 2);
                if ((lane & 3) == 0){
                    int row = wm*64 + mf*16 + half*8 + (lane>>2);
                    prs[wn*128 + row] = s;
                    prq[wn*128 + row] = q;
                }
            }
        __syncthreads();
#pragma unroll
        for (int mf = 0; mf < 4; mf++)
#pragma unroll
            for (int half = 0; half < 2; half++){
                int rowl = wm*64 + mf*16 + half*8 + (lane>>2);
                float S = prs[rowl] + prs[128+rowl] + prs[256+rowl] + prs[384+rowl];
                float Q = prq[rowl] + prq[128+rowl] + prq[256+rowl] + prq[384+rowl];
                float mean = S*(1.f/128.f);
                float rstd = rsqrtf(Q*(1.f/128.f) - mean*mean + 1e-5f);
                size_t mrow = (size_t)(m0 + rowl);
#pragma unroll
                for (int nf = 0; nf < 4; nf++){
                    int col = wn*32 + nf*8 + (lane&3)*2;
                    float v0 = acc[mf][nf][half*2+0];
                    float v1 = acc[mf][nf][half*2+1];
                    size_t off = mrow*128 + col;
                    float2 x2v = *(const float2*)&g_x2[off];
                    float2 o1 = { x2v.x + v0, x2v.y + v1 };
                    *(float2*)&Cext[off] = o1;
                    float d0 = (v0 - mean)*rstd*g_gtp[col]   + g_btp[col];
                    float d1 = (v1 - mean)*rstd*g_gtp[col+1] + g_btp[col+1];
                    uint32_t hi, lo; split2(d0, d1, hi, lo);
                    *(uint32_t*)&g_dnh[off] = hi;
                    *(uint32_t*)&g_dnl[off] = lo;
                }
            }
    } else {
#pragma unroll
        for (int mf = 0; mf < 4; mf++){
#pragma unroll
            for (int nf = 0; nf < 4; nf++){
                int row = m0 + wm*64 + mf*16 + (lane>>2);
                int col = n0 + wn*32 + nf*8 + (lane&3)*2;
#pragma unroll
                for (int half = 0; half < 2; half++){
                    int r2 = row + half*8;
                    float v0 = acc[mf][nf][half*2+0];
                    float v1 = acc[mf][nf][half*2+1];
                    size_t off = (size_t)r2*NN + col;
                    if (MODE == 0){
                        float2 xc = *(const float2*)&g_xc[off];
                        float o0 = v0 + g_bcp[col]   + xc.x;
                        float o1 = v1 + g_bcp[col+1] + xc.y;
                        float2 o = { o0, o1 };
                        *(float2*)&g_x2[off] = o;
                        uint32_t hi, lo; split2(o0, o1, hi, lo);
                        *(uint32_t*)&g_x2h[off] = hi;
                        *(uint32_t*)&g_x2l[off] = lo;
                    } else if (MODE == 1){
                        float2 o = { v0, v1 };
                        *(float2*)&g_xeig[off] = o;
                    } else if (MODE == 3){
                        float o0 = gelu_f(v0 + biasExt[col]);
                        float o1 = gelu_f(v1 + biasExt[col+1]);
                        uint32_t hi, lo; split2(o0, o1, hi, lo);
                        *(uint32_t*)&g_h1h[off] = hi;
                        *(uint32_t*)&g_h1l[off] = lo;
                    } else {
                        float2 p = *(const float2*)&Cext[off];
                        float2 o = { p.x + v0 + g_b2p[col], p.y + v1 + g_b2p[col+1] };
                        *(float2*)&Cext[off] = o;
                    }
                }
            }
        }
        if (MODE == 1){
            // deterministic column partials for spatial mean
            __syncthreads();
            float* ps = (float*)smc;     // [2][128]
#pragma unroll
            for (int nf = 0; nf < 4; nf++)
#pragma unroll
                for (int j = 0; j < 2; j++){
                    float cs = 0.f;
#pragma unroll
                    for (int mf = 0; mf < 4; mf++)
#pragma unroll
                        for (int half = 0; half < 2; half++)
                            cs += acc[mf][nf][half*2+j];
                    cs += __shfl_xor_sync(0xffffffffu, cs, 4);
                    cs += __shfl_xor_sync(0xffffffffu, cs, 8);
                    cs += __shfl_xor_sync(0xffffffffu, cs, 16);
                    if ((lane >> 2) == 0)
                        ps[wm*128 + wn*32 + nf*8 + lane*2 + j] = cs;
                }
            __syncthreads();
            if (tid < 128)
                g_partial[(size_t)blockIdx.y*128 + tid] = ps[tid] + ps[128 + tid];
        }
    }
}

// ---------------- finish spatial mean -------------------------------------------
__global__ void k_mean2()
{
    int bt = blockIdx.x, c = threadIdx.x;
    float s = 0.f;
    for (int j = 0; j < 32; j++) s += g_partial[(size_t)(bt*32+j)*128 + c];
    g_xmean[bt*128 + c] = s * (1.f/4096.f);
}

// ---------------- tiny sequential part ------------------------------------------
__global__ void k_seq(const float* __restrict__ flux_re, const float* __restrict__ flux_im,
                      const float* __restrict__ dt_seq, const float* __restrict__ lam_flux_raw,
                      const float* __restrict__ Wsrc_re, const float* __restrict__ Wsrc_im,
                      const float* __restrict__ w_gate, const float* __restrict__ b_gate,
                      const float* __restrict__ lam_re_raw, const float* __restrict__ lam_im,
                      float* __restrict__ out3, int write_out3)
{
    __shared__ float fre[2][16][64], fim[2][16][64];
    int b = threadIdx.x >> 6, d = threadIdx.x & 63;
    float lamf = softplus_f(lam_flux_raw[d]);
    float vr = flux_re[b*64+d], vi = flux_im[b*64+d];
    for (int t = 0; t < 16; t++){
        float dt = dt_seq[b*16+t];
        float Af = expf(-lamf*dt);
        int bt = b*16 + t;
        float xr = g_xmean[bt*128 + 2*d], xi = g_xmean[bt*128 + 2*d + 1];
        vr = Af*vr + xr*dt;
        vi = Af*vi + xi*dt;
        fre[b][t][d] = vr; fim[b][t][d] = vi;
    }
    __syncthreads();
    int e = d;
    float lr = -softplus_f(lam_re_raw[e]);
    float li = lam_im[e];
    float inv = 1.f/(lr*lr + li*li);
    float wg = w_gate[e], bg = b_gate[e];
    for (int t = 0; t < 16; t++){
        float sr = 0.f, si = 0.f;
        for (int dd = 0; dd < 64; dd++){
            float wr = Wsrc_re[dd*64+e], wi = Wsrc_im[dd*64+e];
            float fr = fre[b][t][dd], fi = fim[b][t][dd];
            sr += fr*wr - fi*wi;
            si += fr*wi + fi*wr;
        }
        float gate = 1.f/(1.f + expf(-(fre[b][t][e]*wg + bg)));
        float dt = dt_seq[b*16+t];
        float er = expf(lr*dt);
        float odr = er*cosf(li*dt), odi = er*sinf(li*dt);
        float nr = odr - 1.f, ni = odi;
        float ofr = (nr*lr + ni*li)*inv;
        float ofi = (ni*lr - nr*li)*inv;
        int idx = (b*16+t)*64 + e;
        g_od[2*idx] = odr;        g_od[2*idx+1] = odi;
        g_cA[2*idx] = gate*ofr;   g_cA[2*idx+1] = gate*ofi;
        float s1r = sr*(1.f-gate), s1i = si*(1.f-gate);
        g_cB[2*idx]   = s1r*ofr - s1i*ofi;
        g_cB[2*idx+1] = s1r*ofi + s1i*ofr;
    }
    if (write_out3){
        out3[(b*64+e)*2+0] = fre[b][15][e];
        out3[(b*64+e)*2+1] = fim[b][15][e];
    }
}

// ---------------- per-(b,h,w,e) recurrence; writes uout split planes ------------
__global__ void k_scan(const float* __restrict__ h_re, const float* __restrict__ h_im,
                       float* __restrict__ out2, int write_out2)
{
    int bh = blockIdx.x;
    int b = bh >> 6, h = bh & 63;
    int w = (blockIdx.y << 2) + (threadIdx.x >> 6);
    int e = threadIdx.x & 63;
    __shared__ float s_od[16][128], s_cA[16][128], s_cB[16][128];
    for (int i = threadIdx.x; i < 16*128; i += 256){
        int t = i>>7, c = i&127;
        s_od[t][c] = g_od[b*2048 + i];
        s_cA[t][c] = g_cA[b*2048 + i];
        s_cB[t][c] = g_cB[b*2048 + i];
    }
    __syncthreads();
    int hw = h*64 + w;
    size_t hidx = ((size_t)(b*64 + h)*64 + w)*64 + e;
    float vr = h_re[hidx], vi = h_im[hidx];
    for (int t = 0; t < 16; t++){
        size_t xoff = (((size_t)(b*16+t)*4096 + hw)*64 + e)*2;
        float xr = g_xeig[xoff], xi = g_xeig[xoff+1];
        float odr = s_od[t][2*e], odi = s_od[t][2*e+1];
        float car = s_cA[t][2*e], cai = s_cA[t][2*e+1];
        float cbr = s_cB[t][2*e], cbi = s_cB[t][2*e+1];
        float ur = xr*car - xi*cai + cbr;
        float ui = xr*cai + xi*car + cbi;
        float nvr = odr*vr - odi*vi + ur;
        float nvi = odr*vi + odi*vr + ui;
        vr = nvr; vi = nvi;
        uint32_t hi, lo; split2(vr, vi, hi, lo);
        *(uint32_t*)&g_uouth[xoff] = hi;
        *(uint32_t*)&g_uoutl[xoff] = lo;
    }
    if (write_out2){
        out2[hidx*2]   = vr;
        out2[hidx*2+1] = vi;
    }
}

// ---------------- launch ---------------------------------------------------------
extern "C" void kernel_launch(void* const* d_in, const int* in_sizes, int n_in,
                              void* d_out, int out_size)
{
    const float* x_re   = (const float*)d_in[0];
    const float* x_im   = (const float*)d_in[1];
    const float* h_re   = (const float*)d_in[2];
    const float* h_im   = (const float*)d_in[3];
    const float* flux_re= (const float*)d_in[4];
    const float* flux_im= (const float*)d_in[5];
    const float* dt_seq = (const float*)d_in[6];
    const float* g_s    = (const float*)d_in[7];
    const float* b_s    = (const float*)d_in[8];
    const float* Wc     = (const float*)d_in[9];
    const float* bc     = (const float*)d_in[10];
    const float* g_t    = (const float*)d_in[11];
    const float* b_t    = (const float*)d_in[12];
    const float* E_re   = (const float*)d_in[13];
    const float* E_im   = (const float*)d_in[14];
    const float* Dec_re = (const float*)d_in[15];
    const float* Dec_im = (const float*)d_in[16];
    const float* lam_flux_raw = (const float*)d_in[17];
    const float* Wsrc_re= (const float*)d_in[18];
    const float* Wsrc_im= (const float*)d_in[19];
    const float* w_gate = (const float*)d_in[20];
    const float* b_gate = (const float*)d_in[21];
    const float* lam_re_raw = (const float*)d_in[22];
    const float* lam_im = (const float*)d_in[23];
    const float* W1     = (const float*)d_in[24];
    const float* b1     = (const float*)d_in[25];
    const float* W2     = (const float*)d_in[26];
    const float* b2     = (const float*)d_in[27];

    float* out = (float*)d_out;
    const int Z_ELEMS  = 2*16*64*64*64*2;
    const int H_ELEMS  = 2*64*64*64*2;
    const int F_ELEMS  = 2*64*2;
    int full = (out_size >= Z_ELEMS + H_ELEMS + F_ELEMS) ? 1 : 0;
    float* out2 = out + Z_ELEMS;
    float* out3 = out + Z_ELEMS + H_ELEMS;

    const int SMEMSZ = 3*32768;   // 3 stages x (16KB A + 16KB B)
    cudaFuncSetAttribute(k_mma<0,1152,128>, cudaFuncAttributeMaxDynamicSharedMemorySize, SMEMSZ);
    cudaFuncSetAttribute(k_mma<1, 128,128>, cudaFuncAttributeMaxDynamicSharedMemorySize, SMEMSZ);
    cudaFuncSetAttribute(k_mma<2, 128,128>, cudaFuncAttributeMaxDynamicSharedMemorySize, SMEMSZ);
    cudaFuncSetAttribute(k_mma<3, 128,512>, cudaFuncAttributeMaxDynamicSharedMemorySize, SMEMSZ);
    cudaFuncSetAttribute(k_mma<4, 512,128>, cudaFuncAttributeMaxDynamicSharedMemorySize, SMEMSZ);

    k_prep<<<256,256>>>(Wc, bc, E_re, E_im, Dec_re, Dec_im, W1, W2, b2, g_t, b_t);
    k_ln<<<dim3(32,66),256>>>(x_re, x_im, g_s, b_s);
    k_mma<0,1152,128><<<dim3(1,1024),256,SMEMSZ>>>(nullptr, nullptr);  // conv -> x2 (+split)
    k_mma<1, 128,128><<<dim3(1,1024),256,SMEMSZ>>>(nullptr, nullptr);  // xeig (+mean partials)
    k_mean2<<<32,128>>>();
    k_seq<<<1,128>>>(flux_re, flux_im, dt_seq, lam_flux_raw, Wsrc_re, Wsrc_im,
                     w_gate, b_gate, lam_re_raw, lam_im, out3, full);
    k_scan<<<dim3(128,16),256>>>(h_re, h_im, out2, full);
    k_mma<2, 128,128><<<dim3(1,1024),256,SMEMSZ>>>(out, nullptr);      // dec: out1 + dn-split
    k_mma<3, 128,512><<<dim3(4,1024),256,SMEMSZ>>>(nullptr, b1);       // h1 split
    k_mma<4, 512,128><<<dim3(1,1024),256,SMEMSZ>>>(out, nullptr);      // out += h1@W2 + b2
}

// round 6
// speedup vs baseline: 2.7695x; 1.0646x over previous
#include <cuda_runtime.h>
#include <cuda_bf16.h>
#include <cstdint>
#include <cstddef>

#define B_  2
#define T_  16
#define D_  64
#define BT_ 32
#define M_  131072

// ---------------- scratch (device globals) --------------------------------------
__device__ __align__(16) __nv_bfloat16 g_xnph[32*66*66*128], g_xnpl[32*66*66*128];
__device__ float g_xc  [(size_t)M_*128];
__device__ float g_x2  [(size_t)M_*128];
__device__ float g_xeig[(size_t)M_*128];
__device__ __align__(16) __nv_bfloat16 g_uouth[(size_t)M_*128], g_uoutl[(size_t)M_*128];
__device__ __align__(16) __nv_bfloat16 g_h1h[(size_t)M_*512],  g_h1l[(size_t)M_*512];

// bf16 weight smem-images: per 32-k chunk per n-row: 128B = [hi 32 | lo 32] bf16,
// 16B-chunk XOR swizzle (chunk ^ (n&7)) baked in.
__device__ __align__(16) __nv_bfloat16 g_BcI[128*36*64];
__device__ __align__(16) __nv_bfloat16 g_BEI[128*4*64];
__device__ __align__(16) __nv_bfloat16 g_BDI[128*4*64];
__device__ __align__(16) __nv_bfloat16 g_B1I[512*4*64];
__device__ __align__(16) __nv_bfloat16 g_B2I[128*16*64];

__device__ float g_bcp [128];
__device__ float g_b2p [128];
__device__ float g_gtp [128];
__device__ float g_btp [128];
__device__ float g_partial[1024*128];
__device__ float g_xmean[32*128];
__device__ float g_od[2*BT_*64];
__device__ float g_cA[2*BT_*64];
__device__ float g_cB[2*BT_*64];

__device__ __forceinline__ float softplus_f(float x){
    return (x > 20.f) ? x : log1pf(expf(x));
}
__device__ __forceinline__ float gelu_f(float x){
    float x3 = x*x*x;
    return 0.5f*x*(1.f + tanhf(0.7978845608028654f*(x + 0.044715f*x3)));
}
__device__ __forceinline__ uint32_t smem_u32(const void* p){
    return (uint32_t)__cvta_generic_to_shared(p);
}
__device__ __forceinline__ void split2(float v0, float v1, uint32_t& hi, uint32_t& lo){
    __nv_bfloat16 h0 = __float2bfloat16(v0), h1 = __float2bfloat16(v1);
    __nv_bfloat16 l0 = __float2bfloat16(v0 - __bfloat162float(h0));
    __nv_bfloat16 l1 = __float2bfloat16(v1 - __bfloat162float(h1));
    __nv_bfloat162 hh; hh.x = h0; hh.y = h1; hi = *(uint32_t*)&hh;
    __nv_bfloat162 ll; ll.x = l0; ll.y = l1; lo = *(uint32_t*)&ll;
}

#define LDX4(r0,r1,r2,r3,addr) \
    asm volatile("ldmatrix.sync.aligned.m8n8.x4.shared.b16 {%0,%1,%2,%3},[%4];" \
        : "=r"(r0),"=r"(r1),"=r"(r2),"=r"(r3) : "r"(addr))
#define MMA16816(c, a, b) \
    asm volatile("mma.sync.aligned.m16n8k16.row.col.f32.bf16.bf16.f32 " \
        "{%0,%1,%2,%3},{%4,%5,%6,%7},{%8,%9},{%0,%1,%2,%3};" \
        : "+f"((c)[0]),"+f"((c)[1]),"+f"((c)[2]),"+f"((c)[3]) \
        : "r"((a)[0]),"r"((a)[1]),"r"((a)[2]),"r"((a)[3]),"r"((b)[0]),"r"((b)[1]))
#define CP_ASYNC16(saddr, gptr) \
    asm volatile("cp.async.cg.shared.global [%0], [%1], 16;" \
        :: "r"(saddr), "l"((const void*)(gptr)) : "memory")
#define CP_COMMIT()  asm volatile("cp.async.commit_group;" ::: "memory")
#define CP_WAIT0()   asm volatile("cp.async.wait_group 0;" ::: "memory")
#define CP_WAIT1()   asm volatile("cp.async.wait_group 1;" ::: "memory")

__device__ __forceinline__ void img_put(__nv_bfloat16* img, int NCh, int n, int k, float v){
    int kc = k >> 5, kl = k & 31;
    int c  = kl >> 3;
    size_t base = ((size_t)n*NCh + kc)*64;
    __nv_bfloat16 h = __float2bfloat16(v);
    float rem = v - __bfloat162float(h);
    img[base + (((c  )^(n&7))<<3) + (kl&7)] = h;
    img[base + (((c+4)^(n&7))<<3) + (kl&7)] = __float2bfloat16(rem);
}

// ---------------- prep ----------------------------------------------------------
__global__ void k_prep(const float* __restrict__ Wc, const float* __restrict__ bc,
                       const float* __restrict__ E_re, const float* __restrict__ E_im,
                       const float* __restrict__ Dec_re, const float* __restrict__ Dec_im,
                       const float* __restrict__ W1, const float* __restrict__ W2,
                       const float* __restrict__ b2, const float* __restrict__ g_t,
                       const float* __restrict__ b_t)
{
    int stride = gridDim.x*blockDim.x;
    int idx = blockIdx.x*blockDim.x + threadIdx.x;
    for (int i = idx; i < 128*1152; i += stride){
        int k = i % 1152, n = i / 1152;
        int p = k >> 7, icp = k & 127;
        int d = icp>>1, r = icp&1, e = n>>1, s = n&1;
        img_put(g_BcI, 36, n, k, Wc[(p*128 + (d + 64*r))*128 + (e + 64*s)]);
    }
    for (int i = idx; i < 128*128; i += stride){
        int k = i & 127, n = i >> 7;
        int e = n>>1, s = n&1, d = k>>1, r = k&1;
        float ve, vd;
        if (s==0){ ve = (r==0)?  E_re[d*64+e]   : -E_im[d*64+e];
                   vd = (r==0)?  Dec_re[d*64+e] : -Dec_im[d*64+e]; }
        else     { ve = (r==0)?  E_im[d*64+e]   :  E_re[d*64+e];
                   vd = (r==0)?  Dec_im[d*64+e] :  Dec_re[d*64+e]; }
        img_put(g_BEI, 4, n, k, ve);
        img_put(g_BDI, 4, n, k, vd);
    }
    for (int i = idx; i < 512*128; i += stride){
        int k = i & 127, f = i >> 7;
        int e = k>>1, r = k&1;
        img_put(g_B1I, 4, f, k, W1[(e + 64*r)*512 + f]);
    }
    for (int i = idx; i < 128*512; i += stride){
        int k = i & 511, n = i >> 9;
        int e = n>>1, s = n&1;
        img_put(g_B2I, 16, n, k, W2[k*128 + (e + 64*s)]);
    }
    for (int i = idx; i < 128; i += stride){
        int e = i>>1, r = i&1;
        g_bcp[i] = bc[e + 64*r];
        g_b2p[i] = b2[e + 64*r];
        g_gtp[i] = g_t[e + 64*r];
        g_btp[i] = b_t[e + 64*r];
    }
}

// ------------- LN + transpose; writes bf16 split conv image + fp32 residual -----
__global__ void k_ln(const float* __restrict__ x_re, const float* __restrict__ x_im,
                     const float* __restrict__ g_s, const float* __restrict__ b_s)
{
    int bt = blockIdx.x;   // 0..31
    int hy = blockIdx.y;   // 0..65
    if (hy >= 64){
        int row = (hy==64) ? 0 : 65;
        size_t base = ((size_t)(bt*66 + row)*66)*128;
        for (int i = threadIdx.x; i < 66*128; i += blockDim.x){
            g_xnph[base + i] = __float2bfloat16(0.f);
            g_xnpl[base + i] = __float2bfloat16(0.f);
        }
        return;
    }
    int h = hy;
    __shared__ float sre[64][65], sim[64][65];
    __shared__ float smean[64], srs[64];
    const float* xr = x_re + (size_t)bt*64*4096 + h*64;
    const float* xi = x_im + (size_t)bt*64*4096 + h*64;
    for (int i = threadIdx.x; i < 4096; i += 256){
        int e = i>>6, w = i&63;
        sre[e][w] = xr[(size_t)e*4096 + w];
        sim[e][w] = xi[(size_t)e*4096 + w];
    }
    __syncthreads();
    int w = threadIdx.x>>2, part = threadIdx.x&3;
    float s = 0.f, s2 = 0.f;
    for (int e = part*16; e < part*16+16; e++){
        float a = sre[e][w], b = sim[e][w];
        s += a + b; s2 += a*a + b*b;
    }
    s  += __shfl_xor_sync(0xffffffffu, s, 1);  s2 += __shfl_xor_sync(0xffffffffu, s2, 1);
    s  += __shfl_xor_sync(0xffffffffu, s, 2);  s2 += __shfl_xor_sync(0xffffffffu, s2, 2);
    if (part == 0){
        float m = s*(1.f/128.f);
        float v = s2*(1.f/128.f) - m*m;
        smean[w] = m; srs[w] = rsqrtf(v + 1e-5f);
    }
    __syncthreads();
    size_t xnb = ((size_t)(bt*66 + h+1)*66 + 1)*128;
    float* xcp = &g_xc[((size_t)(bt*64 + h)*64)*128];
    for (int i = threadIdx.x; i < 4096; i += 256){
        int w2 = i>>6, e = i&63;
        int cp2 = e*2;
        float r0 = sre[e][w2], r1 = sim[e][w2];
        float mm = smean[w2], rr = srs[w2];
        float n0 = (r0 - mm)*rr*g_s[e]    + b_s[e];
        float n1 = (r1 - mm)*rr*g_s[e+64] + b_s[e+64];
        uint32_t hi, lo; split2(n0, n1, hi, lo);
        size_t off = xnb + (size_t)w2*128 + cp2;
        *(uint32_t*)&g_xnph[off] = hi;
        *(uint32_t*)&g_xnpl[off] = lo;
        float2 rc = { r0, r1 };
        *(float2*)&xcp[(size_t)w2*128 + cp2] = rc;
    }
    if (threadIdx.x < 128){
        size_t bL = ((size_t)(bt*66 + h+1)*66 + 0 )*128 + threadIdx.x;
        size_t bR = ((size_t)(bt*66 + h+1)*66 + 65)*128 + threadIdx.x;
        g_xnph[bL] = __float2bfloat16(0.f);  g_xnpl[bL] = __float2bfloat16(0.f);
        g_xnph[bR] = __float2bfloat16(0.f);  g_xnpl[bR] = __float2bfloat16(0.f);
    }
}

// ---------------- bf16-split tensor-core GEMM, cp.async 3-stage -----------------
// MODE 0: conv im2col -> x2 tile -> (fused) xeig = x2 @ E  (+ mean partials)
// MODE 2: dec = uout @ Dec -> out1 = x2+dec; dn=LN(dec) -> (fused) h1 = gelu(dn@W1+b1)
// MODE 4: out += h1 @ W2 + b2p
template<int MODE, int KK, int NN>
__global__ __launch_bounds__(256, 2) void k_mma(float* __restrict__ Cext,
                                                const float* __restrict__ biasExt)
{
    extern __shared__ char smc[];
    const int tid = threadIdx.x, lane = tid & 31, wid = tid >> 5;
    const int wm = wid & 1, wn = wid >> 1;
    const int m0 = blockIdx.y*128, n0 = blockIdx.x*128;
    const int NC = KK/32;

    const __nv_bfloat16* Ah = (MODE==2) ? g_uouth : (MODE==4) ? g_h1h : (const __nv_bfloat16*)nullptr;
    const __nv_bfloat16* Al = (MODE==2) ? g_uoutl : (MODE==4) ? g_h1l : (const __nv_bfloat16*)nullptr;
    const __nv_bfloat16* Bimg = (MODE==0) ? g_BcI : (MODE==2) ? g_BDI : g_B2I;

    uint32_t sbase = smem_u32(smc);
    float acc[4][4][4];
#pragma unroll
    for (int i=0;i<4;i++)
#pragma unroll
        for (int j=0;j<4;j++)
#pragma unroll
            for (int q=0;q<4;q++) acc[i][j][q] = 0.f;

    auto load_stage = [&](int chnk, int s){
        uint32_t sA = sbase + (uint32_t)s*32768u;
        uint32_t sB = sA + 16384u;
        int k0 = chnk*32;
#pragma unroll
        for (int q = 0; q < 4; q++){
            int ca = q*256 + tid;
            int r = ca >> 3, ch = ca & 7;
            const __nv_bfloat16* src;
            if (MODE == 0){
                int m = m0 + r;
                int bt = m >> 12, hh = (m>>6)&63, ww = m&63;
                int p = k0 >> 7; int ky = p/3, kx = p - 3*ky;
                const __nv_bfloat16* pl = (ch < 4) ? g_xnph : g_xnpl;
                src = &pl[(((size_t)(bt*66 + hh + ky))*66 + (ww + kx))*128
                          + (k0 & 127) + (ch&3)*8];
            } else {
                const __nv_bfloat16* pl = (ch < 4) ? Ah : Al;
                src = &pl[(size_t)(m0 + r)*KK + k0 + (ch&3)*8];
            }
            CP_ASYNC16(sA + r*128 + (((uint32_t)(ch ^ (r&7)))<<4), src);
        }
#pragma unroll
        for (int q = 0; q < 4; q++){
            int cb = q*256 + tid;
            int r = cb >> 3, ch = cb & 7;
            const __nv_bfloat16* src = Bimg + ((size_t)(n0 + r)*NC + chnk)*64 + ch*8;
            CP_ASYNC16(sB + r*128 + ch*16, src);   // swizzle baked into image
        }
        CP_COMMIT();
    };

    // generic B-image loader into explicit smem stage (for fused second GEMMs)
    auto loadB2 = [&](const __nv_bfloat16* img, int NCimg, int nbase, int kc, uint32_t dstoff){
#pragma unroll
        for (int q = 0; q < 4; q++){
            int cb = q*256 + tid;
            int r = cb >> 3, ch = cb & 7;
            CP_ASYNC16(sbase + dstoff + r*128 + ch*16,
                       img + ((size_t)(nbase + r)*NCimg + kc)*64 + ch*8);
        }
    };

    auto compute_chunk = [&](uint32_t sA, uint32_t sB){
        const int sel = lane >> 3, l7 = lane & 7;
#pragma unroll
        for (int h = 0; h < 2; h++){
            uint32_t ah[4][4], al[4][4];
#pragma unroll
            for (int mf = 0; mf < 4; mf++){
                int rowl = wm*64 + mf*16 + l7 + ((sel&1)<<3);
                int ch   = 2*h + ((sel>>1)&1);
                uint32_t ad = sA + rowl*128 + (((ch  )^(rowl&7))<<4);
                LDX4(ah[mf][0],ah[mf][1],ah[mf][2],ah[mf][3], ad);
                uint32_t ad2 = sA + rowl*128 + (((ch+4)^(rowl&7))<<4);
                LDX4(al[mf][0],al[mf][1],al[mf][2],al[mf][3], ad2);
            }
            uint32_t bh[4][2], bl[4][2];
#pragma unroll
            for (int q = 0; q < 2; q++){
                int rowl = wn*32 + q*16 + l7 + (((sel>>1)&1)<<3);
                int ch   = 2*h + (sel&1);
                uint32_t bd = sB + rowl*128 + (((ch  )^(rowl&7))<<4);
                LDX4(bh[2*q][0],bh[2*q][1],bh[2*q+1][0],bh[2*q+1][1], bd);
                uint32_t bd2 = sB + rowl*128 + (((ch+4)^(rowl&7))<<4);
                LDX4(bl[2*q][0],bl[2*q][1],bl[2*q+1][0],bl[2*q+1][1], bd2);
            }
#pragma unroll
            for (int mf = 0; mf < 4; mf++)
#pragma unroll
                for (int nf = 0; nf < 4; nf++){
                    MMA16816(acc[mf][nf], ah[mf], bh[nf]);
                    MMA16816(acc[mf][nf], ah[mf], bl[nf]);
                    MMA16816(acc[mf][nf], al[mf], bh[nf]);
                }
        }
    };

    // ---------------- mainloop (first GEMM) ----------------
    load_stage(0, 0);
    if (NC > 1) load_stage(1, 1);
    for (int chnk = 0; chnk < NC; chnk++){
        int s = chnk % 3;
        if (chnk < NC-1) CP_WAIT1(); else CP_WAIT0();
        __syncthreads();
        if (chnk + 2 < NC) load_stage(chnk+2, (chnk+2)%3);
        compute_chunk(sbase + (uint32_t)s*32768u, sbase + (uint32_t)s*32768u + 16384u);
    }
    __syncthreads();   // all warps done with all stages before smem reuse

    // helper: write a split bf16 pair into the smem A2 image (64KB at offset 0)
    auto a2_put = [&](int rowl, int col, float v0, float v1){
        uint32_t hi, lo; split2(v0, v1, hi, lo);
        int kc = col >> 5, kl = col & 31, c = kl >> 3, by = (kl & 7)*2;
        char* base = smc + kc*16384 + rowl*128;
        *(uint32_t*)(base + (((c  )^(rowl&7))<<4) + by) = hi;
        *(uint32_t*)(base + (((c+4)^(rowl&7))<<4) + by) = lo;
    };

    if (MODE == 0){
        // phase 1: x2 = acc + bc + xc -> gmem fp32 + smem A2 split image
#pragma unroll
        for (int mf = 0; mf < 4; mf++)
#pragma unroll
            for (int half = 0; half < 2; half++){
                int rowl = wm*64 + mf*16 + half*8 + (lane>>2);
#pragma unroll
                for (int nf = 0; nf < 4; nf++){
                    int col = wn*32 + nf*8 + (lane&3)*2;
                    size_t off = (size_t)(m0 + rowl)*128 + col;
                    float2 xc = *(const float2*)&g_xc[off];
                    float o0 = acc[mf][nf][half*2+0] + g_bcp[col]   + xc.x;
                    float o1 = acc[mf][nf][half*2+1] + g_bcp[col+1] + xc.y;
                    float2 o = { o0, o1 };
                    *(float2*)&g_x2[off] = o;
                    a2_put(rowl, col, o0, o1);
                }
            }
        // reset acc for second GEMM
#pragma unroll
        for (int i=0;i<4;i++)
#pragma unroll
            for (int j=0;j<4;j++)
#pragma unroll
                for (int q=0;q<4;q++) acc[i][j][q] = 0.f;
        __syncthreads();
        // phase 2: xeig = x2_tile @ E (4 chunks, A from smem, B half/half)
        loadB2(g_BEI, 4, 0, 0, 65536u); loadB2(g_BEI, 4, 0, 1, 81920u); CP_COMMIT();
        CP_WAIT0(); __syncthreads();
        compute_chunk(sbase +     0u, sbase + 65536u);
        compute_chunk(sbase + 16384u, sbase + 81920u);
        __syncthreads();
        loadB2(g_BEI, 4, 0, 2, 65536u); loadB2(g_BEI, 4, 0, 3, 81920u); CP_COMMIT();
        CP_WAIT0(); __syncthreads();
        compute_chunk(sbase + 32768u, sbase + 65536u);
        compute_chunk(sbase + 49152u, sbase + 81920u);
        // epilogue: write xeig fp32 + column partials
#pragma unroll
        for (int mf = 0; mf < 4; mf++)
#pragma unroll
            for (int nf = 0; nf < 4; nf++){
                int row = m0 + wm*64 + mf*16 + (lane>>2);
                int col = wn*32 + nf*8 + (lane&3)*2;
#pragma unroll
                for (int half = 0; half < 2; half++){
                    size_t off = (size_t)(row + half*8)*128 + col;
                    float2 o = { acc[mf][nf][half*2+0], acc[mf][nf][half*2+1] };
                    *(float2*)&g_xeig[off] = o;
                }
            }
        __syncthreads();
        {
            float* ps = (float*)smc;
#pragma unroll
            for (int nf = 0; nf < 4; nf++)
#pragma unroll
                for (int j = 0; j < 2; j++){
                    float cs = 0.f;
#pragma unroll
                    for (int mf = 0; mf < 4; mf++)
#pragma unroll
                        for (int half = 0; half < 2; half++)
                            cs += acc[mf][nf][half*2+j];
                    cs += __shfl_xor_sync(0xffffffffu, cs, 4);
                    cs += __shfl_xor_sync(0xffffffffu, cs, 8);
                    cs += __shfl_xor_sync(0xffffffffu, cs, 16);
                    if ((lane >> 2) == 0)
                        ps[wm*128 + wn*32 + nf*8 + lane*2 + j] = cs;
                }
            __syncthreads();
            if (tid < 128)
                g_partial[(size_t)blockIdx.y*128 + tid] = ps[tid] + ps[128 + tid];
        }
    } else if (MODE == 2){
        // phase 1: LN stats over dec tile (partials in high smem region)
        float* prs = (float*)(smc + 65536);
        float* prq = prs + 512;
#pragma unroll
        for (int mf = 0; mf < 4; mf++)
#pragma unroll
            for (int half = 0; half < 2; half++){
                float s = 0.f, q = 0.f;
#pragma unroll
                for (int nf = 0; nf < 4; nf++)
#pragma unroll
                    for (int j = 0; j < 2; j++){
                        float v = acc[mf][nf][half*2+j];
                        s += v; q += v*v;
                    }
                s += __shfl_xor_sync(0xffffffffu, s, 1);
                s += __shfl_xor_sync(0xffffffffu, s, 2);
                q += __shfl_xor_sync(0xffffffffu, q, 1);
                q += __shfl_xor_sync(0xffffffffu, q, 2);
                if ((lane & 3) == 0){
                    int row = wm*64 + mf*16 + half*8 + (lane>>2);
                    prs[wn*128 + row] = s;
                    prq[wn*128 + row] = q;
                }
            }
        __syncthreads();
        // phase 2: out1 = x2 + dec ; dn -> smem A2 image
#pragma unroll
        for (int mf = 0; mf < 4; mf++)
#pragma unroll
            for (int half = 0; half < 2; half++){
                int rowl = wm*64 + mf*16 + half*8 + (lane>>2);
                float S = prs[rowl] + prs[128+rowl] + prs[256+rowl] + prs[384+rowl];
                float Q = prq[rowl] + prq[128+rowl] + prq[256+rowl] + prq[384+rowl];
                float mean = S*(1.f/128.f);
                float rstd = rsqrtf(Q*(1.f/128.f) - mean*mean + 1e-5f);
#pragma unroll
                for (int nf = 0; nf < 4; nf++){
                    int col = wn*32 + nf*8 + (lane&3)*2;
                    float v0 = acc[mf][nf][half*2+0];
                    float v1 = acc[mf][nf][half*2+1];
                    size_t off = (size_t)(m0 + rowl)*128 + col;
                    float2 x2v = *(const float2*)&g_x2[off];
                    float2 o1 = { x2v.x + v0, x2v.y + v1 };
                    *(float2*)&Cext[off] = o1;
                    float d0 = (v0 - mean)*rstd*g_gtp[col]   + g_btp[col];
                    float d1 = (v1 - mean)*rstd*g_gtp[col+1] + g_btp[col+1];
                    a2_put(rowl, col, d0, d1);
                }
            }
        // phase 3: h1 = gelu(dn @ W1 + b1), 4 n-iterations from smem dn
        for (int jn = 0; jn < 4; jn++){
#pragma unroll
            for (int i=0;i<4;i++)
#pragma unroll
                for (int j=0;j<4;j++)
#pragma unroll
                    for (int q=0;q<4;q++) acc[i][j][q] = 0.f;
            __syncthreads();
            loadB2(g_B1I, 4, jn*128, 0, 65536u); loadB2(g_B1I, 4, jn*128, 1, 81920u); CP_COMMIT();
            CP_WAIT0(); __syncthreads();
            compute_chunk(sbase +     0u, sbase + 65536u);
            compute_chunk(sbase + 16384u, sbase + 81920u);
            __syncthreads();
            loadB2(g_B1I, 4, jn*128, 2, 65536u); loadB2(g_B1I, 4, jn*128, 3, 81920u); CP_COMMIT();
            CP_WAIT0(); __syncthreads();
            compute_chunk(sbase + 32768u, sbase + 65536u);
            compute_chunk(sbase + 49152u, sbase + 81920u);
#pragma unroll
            for (int mf = 0; mf < 4; mf++)
#pragma unroll
                for (int nf = 0; nf < 4; nf++){
                    int row = m0 + wm*64 + mf*16 + (lane>>2);
                    int col = jn*128 + wn*32 + nf*8 + (lane&3)*2;
#pragma unroll
                    for (int half = 0; half < 2; half++){
                        float o0 = gelu_f(acc[mf][nf][half*2+0] + biasExt[col]);
                        float o1 = gelu_f(acc[mf][nf][half*2+1] + biasExt[col+1]);
                        uint32_t hi, lo; split2(o0, o1, hi, lo);
                        size_t off = (size_t)(row + half*8)*512 + col;
                        *(uint32_t*)&g_h1h[off] = hi;
                        *(uint32_t*)&g_h1l[off] = lo;
                    }
                }
        }
    } else {   // MODE 4
#pragma unroll
        for (int mf = 0; mf < 4; mf++)
#pragma unroll
            for (int nf = 0; nf < 4; nf++){
                int row = m0 + wm*64 + mf*16 + (lane>>2);
                int col = wn*32 + nf*8 + (lane&3)*2;
#pragma unroll
                for (int half = 0; half < 2; half++){
                    size_t off = (size_t)(row + half*8)*128 + col;
                    float2 p = *(const float2*)&Cext[off];
                    float2 o = { p.x + acc[mf][nf][half*2+0] + g_b2p[col],
                                 p.y + acc[mf][nf][half*2+1] + g_b2p[col+1] };
                    *(float2*)&Cext[off] = o;
                }
            }
    }
}

// ---------------- finish spatial mean -------------------------------------------
__global__ void k_mean2()
{
    int bt = blockIdx.x, c = threadIdx.x;
    float s = 0.f;
    for (int j = 0; j < 32; j++) s += g_partial[(size_t)(bt*32+j)*128 + c];
    g_xmean[bt*128 + c] = s * (1.f/4096.f);
}

// ---------------- tiny sequential part ------------------------------------------
__global__ void k_seq(const float* __restrict__ flux_re, const float* __restrict__ flux_im,
                      const float* __restrict__ dt_seq, const float* __restrict__ lam_flux_raw,
                      const float* __restrict__ Wsrc_re, const float* __restrict__ Wsrc_im,
                      const float* __restrict__ w_gate, const float* __restrict__ b_gate,
                      const float* __restrict__ lam_re_raw, const float* __restrict__ lam_im,
                      float* __restrict__ out3, int write_out3)
{
    __shared__ float fre[2][16][64], fim[2][16][64];
    int b = threadIdx.x >> 6, d = threadIdx.x & 63;
    float lamf = softplus_f(lam_flux_raw[d]);
    float vr = flux_re[b*64+d], vi = flux_im[b*64+d];
    for (int t = 0; t < 16; t++){
        float dt = dt_seq[b*16+t];
        float Af = expf(-lamf*dt);
        int bt = b*16 + t;
        float xr = g_xmean[bt*128 + 2*d], xi = g_xmean[bt*128 + 2*d + 1];
        vr = Af*vr + xr*dt;
        vi = Af*vi + xi*dt;
        fre[b][t][d] = vr; fim[b][t][d] = vi;
    }
    __syncthreads();
    int e = d;
    float lr = -softplus_f(lam_re_raw[e]);
    float li = lam_im[e];
    float inv = 1.f/(lr*lr + li*li);
    float wg = w_gate[e], bg = b_gate[e];
    for (int t = 0; t < 16; t++){
        float sr = 0.f, si = 0.f;
        for (int dd = 0; dd < 64; dd++){
            float wr = Wsrc_re[dd*64+e], wi = Wsrc_im[dd*64+e];
            float fr = fre[b][t][dd], fi = fim[b][t][dd];
            sr += fr*wr - fi*wi;
            si += fr*wi + fi*wr;
        }
        float gate = 1.f/(1.f + expf(-(fre[b][t][e]*wg + bg)));
        float dt = dt_seq[b*16+t];
        float er = expf(lr*dt);
        float odr = er*cosf(li*dt), odi = er*sinf(li*dt);
        float nr = odr - 1.f, ni = odi;
        float ofr = (nr*lr + ni*li)*inv;
        float ofi = (ni*lr - nr*li)*inv;
        int idx = (b*16+t)*64 + e;
        g_od[2*idx] = odr;        g_od[2*idx+1] = odi;
        g_cA[2*idx] = gate*ofr;   g_cA[2*idx+1] = gate*ofi;
        float s1r = sr*(1.f-gate), s1i = si*(1.f-gate);
        g_cB[2*idx]   = s1r*ofr - s1i*ofi;
        g_cB[2*idx+1] = s1r*ofi + s1i*ofr;
    }
    if (write_out3){
        out3[(b*64+e)*2+0] = fre[b][15][e];
        out3[(b*64+e)*2+1] = fim[b][15][e];
    }
}

// ---------------- per-(b,h,w,e) recurrence; writes uout split planes ------------
__global__ void k_scan(const float* __restrict__ h_re, const float* __restrict__ h_im,
                       float* __restrict__ out2, int write_out2)
{
    int bh = blockIdx.x;
    int b = bh >> 6, h = bh & 63;
    int w = (blockIdx.y << 2) + (threadIdx.x >> 6);
    int e = threadIdx.x & 63;
    __shared__ float s_od[16][128], s_cA[16][128], s_cB[16][128];
    for (int i = threadIdx.x; i < 16*128; i += 256){
        int t = i>>7, c = i&127;
        s_od[t][c] = g_od[b*2048 + i];
        s_cA[t][c] = g_cA[b*2048 + i];
        s_cB[t][c] = g_cB[b*2048 + i];
    }
    __syncthreads();
    int hw = h*64 + w;
    size_t hidx = ((size_t)(b*64 + h)*64 + w)*64 + e;
    float vr = h_re[hidx], vi = h_im[hidx];
    for (int t = 0; t < 16; t++){
        size_t xoff = (((size_t)(b*16+t)*4096 + hw)*64 + e)*2;
        float xr = g_xeig[xoff], xi = g_xeig[xoff+1];
        float odr = s_od[t][2*e], odi = s_od[t][2*e+1];
        float car = s_cA[t][2*e], cai = s_cA[t][2*e+1];
        float cbr = s_cB[t][2*e], cbi = s_cB[t][2*e+1];
        float ur = xr*car - xi*cai + cbr;
        float ui = xr*cai + xi*car + cbi;
        float nvr = odr*vr - odi*vi + ur;
        float nvi = odr*vi + odi*vr + ui;
        vr = nvr; vi = nvi;
        uint32_t hi, lo; split2(vr, vi, hi, lo);
        *(uint32_t*)&g_uouth[xoff] = hi;
        *(uint32_t*)&g_uoutl[xoff] = lo;
    }
    if (write_out2){
        out2[hidx*2]   = vr;
        out2[hidx*2+1] = vi;
    }
}

// ---------------- launch ---------------------------------------------------------
extern "C" void kernel_launch(void* const* d_in, const int* in_sizes, int n_in,
                              void* d_out, int out_size)
{
    const float* x_re   = (const float*)d_in[0];
    const float* x_im   = (const float*)d_in[1];
    const float* h_re   = (const float*)d_in[2];
    const float* h_im   = (const float*)d_in[3];
    const float* flux_re= (const float*)d_in[4];
    const float* flux_im= (const float*)d_in[5];
    const float* dt_seq = (const float*)d_in[6];
    const float* g_s    = (const float*)d_in[7];
    const float* b_s    = (const float*)d_in[8];
    const float* Wc     = (const float*)d_in[9];
    const float* bc     = (const float*)d_in[10];
    const float* g_t    = (const float*)d_in[11];
    const float* b_t    = (const float*)d_in[12];
    const float* E_re   = (const float*)d_in[13];
    const float* E_im   = (const float*)d_in[14];
    const float* Dec_re = (const float*)d_in[15];
    const float* Dec_im = (const float*)d_in[16];
    const float* lam_flux_raw = (const float*)d_in[17];
    const float* Wsrc_re= (const float*)d_in[18];
    const float* Wsrc_im= (const float*)d_in[19];
    const float* w_gate = (const float*)d_in[20];
    const float* b_gate = (const float*)d_in[21];
    const float* lam_re_raw = (const float*)d_in[22];
    const float* lam_im = (const float*)d_in[23];
    const float* W1     = (const float*)d_in[24];
    const float* b1     = (const float*)d_in[25];
    const float* W2     = (const float*)d_in[26];
    const float* b2     = (const float*)d_in[27];

    float* out = (float*)d_out;
    const int Z_ELEMS  = 2*16*64*64*64*2;
    const int H_ELEMS  = 2*64*64*64*2;
    const int F_ELEMS  = 2*64*2;
    int full = (out_size >= Z_ELEMS + H_ELEMS + F_ELEMS) ? 1 : 0;
    float* out2 = out + Z_ELEMS;
    float* out3 = out + Z_ELEMS + H_ELEMS;

    const int SMEMSZ = 3*32768;   // 96KB: 3 stages / 64KB A2 image + 32KB B stages
    cudaFuncSetAttribute(k_mma<0,1152,128>, cudaFuncAttributeMaxDynamicSharedMemorySize, SMEMSZ);
    cudaFuncSetAttribute(k_mma<2, 128,128>, cudaFuncAttributeMaxDynamicSharedMemorySize, SMEMSZ);
    cudaFuncSetAttribute(k_mma<4, 512,128>, cudaFuncAttributeMaxDynamicSharedMemorySize, SMEMSZ);

    k_prep<<<256,256>>>(Wc, bc, E_re, E_im, Dec_re, Dec_im, W1, W2, b2, g_t, b_t);
    k_ln<<<dim3(32,66),256>>>(x_re, x_im, g_s, b_s);
    k_mma<0,1152,128><<<dim3(1,1024),256,SMEMSZ>>>(nullptr, nullptr);  // conv -> x2 -> xeig
    k_mean2<<<32,128>>>();
    k_seq<<<1,128>>>(flux_re, flux_im, dt_seq, lam_flux_raw, Wsrc_re, Wsrc_im,
                     w_gate, b_gate, lam_re_raw, lam_im, out3, full);
    k_scan<<<dim3(128,16),256>>>(h_re, h_im, out2, full);
    k_mma<2, 128,128><<<dim3(1,1024),256,SMEMSZ>>>(out, b1);           // dec->out1/dn->h1
    k_mma<4, 512,128><<<dim3(1,1024),256,SMEMSZ>>>(out, nullptr);      // out += h1@W2 + b2
}

// round 7
// speedup vs baseline: 2.9556x; 1.0672x over previous
#include <cuda_runtime.h>
#include <cuda_bf16.h>
#include <cstdint>
#include <cstddef>

#define B_  2
#define T_  16
#define D_  64
#define BT_ 32
#define M_  131072

// ---------------- scratch (device globals) --------------------------------------
__device__ __align__(16) __nv_bfloat16 g_xnph[32*66*66*128], g_xnpl[32*66*66*128];
__device__ float g_xc  [(size_t)M_*128];
__device__ float g_x2  [(size_t)M_*128];
__device__ float g_xeig[(size_t)M_*128];
__device__ __align__(16) __nv_bfloat16 g_uouth[(size_t)M_*128], g_uoutl[(size_t)M_*128];
__device__ __align__(16) __nv_bfloat16 g_h1b[(size_t)M_*512];

// bf16 weight smem-images: per 32-k chunk per n-row: 128B = [hi 32 | lo 32] bf16,
// 16B-chunk XOR swizzle (chunk ^ (n&7)) baked in.
__device__ __align__(16) __nv_bfloat16 g_BcI[128*36*64];
__device__ __align__(16) __nv_bfloat16 g_BEI[128*4*64];
__device__ __align__(16) __nv_bfloat16 g_BDI[128*4*64];
__device__ __align__(16) __nv_bfloat16 g_B1I[512*4*64];
__device__ __align__(16) __nv_bfloat16 g_B2I[128*16*64];

__device__ float g_bcp [128];
__device__ float g_b2p [128];
__device__ float g_gtp [128];
__device__ float g_btp [128];
__device__ float g_partial[1024*128];
__device__ float g_xmean[32*128];
__device__ float g_od[2*BT_*64];
__device__ float g_cA[2*BT_*64];
__device__ float g_cB[2*BT_*64];

__device__ __forceinline__ float softplus_f(float x){
    return (x > 20.f) ? x : log1pf(expf(x));
}
__device__ __forceinline__ float gelu_f(float x){
    float x3 = x*x*x;
    return 0.5f*x*(1.f + tanhf(0.7978845608028654f*(x + 0.044715f*x3)));
}
__device__ __forceinline__ uint32_t smem_u32(const void* p){
    return (uint32_t)__cvta_generic_to_shared(p);
}
__device__ __forceinline__ void split2(float v0, float v1, uint32_t& hi, uint32_t& lo){
    __nv_bfloat16 h0 = __float2bfloat16(v0), h1 = __float2bfloat16(v1);
    __nv_bfloat16 l0 = __float2bfloat16(v0 - __bfloat162float(h0));
    __nv_bfloat16 l1 = __float2bfloat16(v1 - __bfloat162float(h1));
    __nv_bfloat162 hh; hh.x = h0; hh.y = h1; hi = *(uint32_t*)&hh;
    __nv_bfloat162 ll; ll.x = l0; ll.y = l1; lo = *(uint32_t*)&ll;
}

#define LDX4(r0,r1,r2,r3,addr) \
    asm volatile("ldmatrix.sync.aligned.m8n8.x4.shared.b16 {%0,%1,%2,%3},[%4];" \
        : "=r"(r0),"=r"(r1),"=r"(r2),"=r"(r3) : "r"(addr))
#define MMA16816(c, a, b) \
    asm volatile("mma.sync.aligned.m16n8k16.row.col.f32.bf16.bf16.f32 " \
        "{%0,%1,%2,%3},{%4,%5,%6,%7},{%8,%9},{%0,%1,%2,%3};" \
        : "+f"((c)[0]),"+f"((c)[1]),"+f"((c)[2]),"+f"((c)[3]) \
        : "r"((a)[0]),"r"((a)[1]),"r"((a)[2]),"r"((a)[3]),"r"((b)[0]),"r"((b)[1]))
#define CP_ASYNC16(saddr, gptr) \
    asm volatile("cp.async.cg.shared.global [%0], [%1], 16;" \
        :: "r"(saddr), "l"((const void*)(gptr)) : "memory")
#define CP_COMMIT()  asm volatile("cp.async.commit_group;" ::: "memory")
#define CP_WAIT0()   asm volatile("cp.async.wait_group 0;" ::: "memory")
#define CP_WAIT1()   asm volatile("cp.async.wait_group 1;" ::: "memory")

__device__ __forceinline__ void img_put(__nv_bfloat16* img, int NCh, int n, int k, float v){
    int kc = k >> 5, kl = k & 31;
    int c  = kl >> 3;
    size_t base = ((size_t)n*NCh + kc)*64;
    __nv_bfloat16 h = __float2bfloat16(v);
    float rem = v - __bfloat162float(h);
    img[base + (((c  )^(n&7))<<3) + (kl&7)] = h;
    img[base + (((c+4)^(n&7))<<3) + (kl&7)] = __float2bfloat16(rem);
}

// --------- restructured chunk compute: B fragments first, per-mf A + MMAs -------
template<bool USELO>
__device__ __forceinline__ void compute_chunk_f(float (&acc)[4][4][4],
                                                uint32_t sA, uint32_t sB,
                                                int lane, int wm, int wn)
{
    const int sel = lane >> 3, l7 = lane & 7;
    uint32_t bh[2][4][2], bl[2][4][2];
#pragma unroll
    for (int h = 0; h < 2; h++)
#pragma unroll
        for (int q = 0; q < 2; q++){
            int rowl = wn*32 + q*16 + l7 + (((sel>>1)&1)<<3);
            int ch   = 2*h + (sel&1);
            uint32_t bd = sB + rowl*128 + (((ch  )^(rowl&7))<<4);
            LDX4(bh[h][2*q][0],bh[h][2*q][1],bh[h][2*q+1][0],bh[h][2*q+1][1], bd);
            uint32_t bd2 = sB + rowl*128 + (((ch+4)^(rowl&7))<<4);
            LDX4(bl[h][2*q][0],bl[h][2*q][1],bl[h][2*q+1][0],bl[h][2*q+1][1], bd2);
        }
#pragma unroll
    for (int mf = 0; mf < 4; mf++){
#pragma unroll
        for (int h = 0; h < 2; h++){
            uint32_t ah[4], al[4];
            int rowl = wm*64 + mf*16 + l7 + ((sel&1)<<3);
            int ch   = 2*h + ((sel>>1)&1);
            LDX4(ah[0],ah[1],ah[2],ah[3], sA + rowl*128 + (((ch  )^(rowl&7))<<4));
            if (USELO){
                LDX4(al[0],al[1],al[2],al[3], sA + rowl*128 + (((ch+4)^(rowl&7))<<4));
            }
#pragma unroll
            for (int nf = 0; nf < 4; nf++){
                MMA16816(acc[mf][nf], ah, bh[h][nf]);
                MMA16816(acc[mf][nf], ah, bl[h][nf]);
                if (USELO) MMA16816(acc[mf][nf], al, bh[h][nf]);
            }
        }
    }
}

// ---------------- prep ----------------------------------------------------------
__global__ void k_prep(const float* __restrict__ Wc, const float* __restrict__ bc,
                       const float* __restrict__ E_re, const float* __restrict__ E_im,
                       const float* __restrict__ Dec_re, const float* __restrict__ Dec_im,
                       const float* __restrict__ W1, const float* __restrict__ W2,
                       const float* __restrict__ b2, const float* __restrict__ g_t,
                       const float* __restrict__ b_t)
{
    int stride = gridDim.x*blockDim.x;
    int idx = blockIdx.x*blockDim.x + threadIdx.x;
    for (int i = idx; i < 128*1152; i += stride){
        int k = i % 1152, n = i / 1152;
        int p = k >> 7, icp = k & 127;
        int d = icp>>1, r = icp&1, e = n>>1, s = n&1;
        img_put(g_BcI, 36, n, k, Wc[(p*128 + (d + 64*r))*128 + (e + 64*s)]);
    }
    for (int i = idx; i < 128*128; i += stride){
        int k = i & 127, n = i >> 7;
        int e = n>>1, s = n&1, d = k>>1, r = k&1;
        float ve, vd;
        if (s==0){ ve = (r==0)?  E_re[d*64+e]   : -E_im[d*64+e];
                   vd = (r==0)?  Dec_re[d*64+e] : -Dec_im[d*64+e]; }
        else     { ve = (r==0)?  E_im[d*64+e]   :  E_re[d*64+e];
                   vd = (r==0)?  Dec_im[d*64+e] :  Dec_re[d*64+e]; }
        img_put(g_BEI, 4, n, k, ve);
        img_put(g_BDI, 4, n, k, vd);
    }
    for (int i = idx; i < 512*128; i += stride){
        int k = i & 127, f = i >> 7;
        int e = k>>1, r = k&1;
        img_put(g_B1I, 4, f, k, W1[(e + 64*r)*512 + f]);
    }
    for (int i = idx; i < 128*512; i += stride){
        int k = i & 511, n = i >> 9;
        int e = n>>1, s = n&1;
        img_put(g_B2I, 16, n, k, W2[k*128 + (e + 64*s)]);
    }
    for (int i = idx; i < 128; i += stride){
        int e = i>>1, r = i&1;
        g_bcp[i] = bc[e + 64*r];
        g_b2p[i] = b2[e + 64*r];
        g_gtp[i] = g_t[e + 64*r];
        g_btp[i] = b_t[e + 64*r];
    }
}

// ------------- LN + transpose; writes bf16 split conv image + fp32 residual -----
__global__ void k_ln(const float* __restrict__ x_re, const float* __restrict__ x_im,
                     const float* __restrict__ g_s, const float* __restrict__ b_s)
{
    int bt = blockIdx.x;   // 0..31
    int hy = blockIdx.y;   // 0..65
    if (hy >= 64){
        int row = (hy==64) ? 0 : 65;
        size_t base = ((size_t)(bt*66 + row)*66)*128;
        for (int i = threadIdx.x; i < 66*128; i += blockDim.x){
            g_xnph[base + i] = __float2bfloat16(0.f);
            g_xnpl[base + i] = __float2bfloat16(0.f);
        }
        return;
    }
    int h = hy;
    __shared__ float sre[64][65], sim[64][65];
    __shared__ float smean[64], srs[64];
    const float* xr = x_re + (size_t)bt*64*4096 + h*64;
    const float* xi = x_im + (size_t)bt*64*4096 + h*64;
    for (int i = threadIdx.x; i < 4096; i += 256){
        int e = i>>6, w = i&63;
        sre[e][w] = xr[(size_t)e*4096 + w];
        sim[e][w] = xi[(size_t)e*4096 + w];
    }
    __syncthreads();
    int w = threadIdx.x>>2, part = threadIdx.x&3;
    float s = 0.f, s2 = 0.f;
    for (int e = part*16; e < part*16+16; e++){
        float a = sre[e][w], b = sim[e][w];
        s += a + b; s2 += a*a + b*b;
    }
    s  += __shfl_xor_sync(0xffffffffu, s, 1);  s2 += __shfl_xor_sync(0xffffffffu, s2, 1);
    s  += __shfl_xor_sync(0xffffffffu, s, 2);  s2 += __shfl_xor_sync(0xffffffffu, s2, 2);
    if (part == 0){
        float m = s*(1.f/128.f);
        float v = s2*(1.f/128.f) - m*m;
        smean[w] = m; srs[w] = rsqrtf(v + 1e-5f);
    }
    __syncthreads();
    size_t xnb = ((size_t)(bt*66 + h+1)*66 + 1)*128;
    float* xcp = &g_xc[((size_t)(bt*64 + h)*64)*128];
    for (int i = threadIdx.x; i < 4096; i += 256){
        int w2 = i>>6, e = i&63;
        int cp2 = e*2;
        float r0 = sre[e][w2], r1 = sim[e][w2];
        float mm = smean[w2], rr = srs[w2];
        float n0 = (r0 - mm)*rr*g_s[e]    + b_s[e];
        float n1 = (r1 - mm)*rr*g_s[e+64] + b_s[e+64];
        uint32_t hi, lo; split2(n0, n1, hi, lo);
        size_t off = xnb + (size_t)w2*128 + cp2;
        *(uint32_t*)&g_xnph[off] = hi;
        *(uint32_t*)&g_xnpl[off] = lo;
        float2 rc = { r0, r1 };
        *(float2*)&xcp[(size_t)w2*128 + cp2] = rc;
    }
    if (threadIdx.x < 128){
        size_t bL = ((size_t)(bt*66 + h+1)*66 + 0 )*128 + threadIdx.x;
        size_t bR = ((size_t)(bt*66 + h+1)*66 + 65)*128 + threadIdx.x;
        g_xnph[bL] = __float2bfloat16(0.f);  g_xnpl[bL] = __float2bfloat16(0.f);
        g_xnph[bR] = __float2bfloat16(0.f);  g_xnpl[bR] = __float2bfloat16(0.f);
    }
}

// ---------------- bf16-split tensor-core GEMM, cp.async 3-stage -----------------
// MODE 0: conv im2col -> x2 tile -> (fused) xeig = x2 @ E  (+ mean partials)
// MODE 2: dec = uout @ Dec -> out1 = x2+dec; dn=LN(dec) -> (fused) h1 = gelu(dn@W1+b1)
// MODE 4: out += h1 @ W2 + b2p  (2-term: h1 stored bf16-only)
template<int MODE, int KK, int NN>
__global__ __launch_bounds__(256, 2) void k_mma(float* __restrict__ Cext,
                                                const float* __restrict__ biasExt)
{
    extern __shared__ char smc[];
    const int tid = threadIdx.x, lane = tid & 31, wid = tid >> 5;
    const int wm = wid & 1, wn = wid >> 1;
    const int m0 = blockIdx.y*128, n0 = blockIdx.x*128;
    const int NC = KK/32;

    const __nv_bfloat16* Ah = (MODE==2) ? g_uouth : (MODE==4) ? g_h1b : (const __nv_bfloat16*)nullptr;
    const __nv_bfloat16* Al = (MODE==2) ? g_uoutl : (MODE==4) ? g_h1b : (const __nv_bfloat16*)nullptr;
    const __nv_bfloat16* Bimg = (MODE==0) ? g_BcI : (MODE==2) ? g_BDI : g_B2I;

    uint32_t sbase = smem_u32(smc);
    float acc[4][4][4];
#pragma unroll
    for (int i=0;i<4;i++)
#pragma unroll
        for (int j=0;j<4;j++)
#pragma unroll
            for (int q=0;q<4;q++) acc[i][j][q] = 0.f;

    auto load_stage = [&](int chnk, int s){
        uint32_t sA = sbase + (uint32_t)s*32768u;
        uint32_t sB = sA + 16384u;
        int k0 = chnk*32;
#pragma unroll
        for (int q = 0; q < 4; q++){
            int ca = q*256 + tid;
            int r = ca >> 3, ch = ca & 7;
            if (MODE == 4 && ch >= 4) continue;   // hi plane only
            const __nv_bfloat16* src;
            if (MODE == 0){
                int m = m0 + r;
                int bt = m >> 12, hh = (m>>6)&63, ww = m&63;
                int p = k0 >> 7; int ky = p/3, kx = p - 3*ky;
                const __nv_bfloat16* pl = (ch < 4) ? g_xnph : g_xnpl;
                src = &pl[(((size_t)(bt*66 + hh + ky))*66 + (ww + kx))*128
                          + (k0 & 127) + (ch&3)*8];
            } else {
                const __nv_bfloat16* pl = (ch < 4) ? Ah : Al;
                src = &pl[(size_t)(m0 + r)*KK + k0 + (ch&3)*8];
            }
            CP_ASYNC16(sA + r*128 + (((uint32_t)(ch ^ (r&7)))<<4), src);
        }
#pragma unroll
        for (int q = 0; q < 4; q++){
            int cb = q*256 + tid;
            int r = cb >> 3, ch = cb & 7;
            const __nv_bfloat16* src = Bimg + ((size_t)(n0 + r)*NC + chnk)*64 + ch*8;
            CP_ASYNC16(sB + r*128 + ch*16, src);   // swizzle baked into image
        }
        CP_COMMIT();
    };

    // generic B-image loader into explicit smem stage (for fused second GEMMs)
    auto loadB2 = [&](const __nv_bfloat16* img, int NCimg, int nbase, int kc, uint32_t dstoff){
#pragma unroll
        for (int q = 0; q < 4; q++){
            int cb = q*256 + tid;
            int r = cb >> 3, ch = cb & 7;
            CP_ASYNC16(sbase + dstoff + r*128 + ch*16,
                       img + ((size_t)(nbase + r)*NCimg + kc)*64 + ch*8);
        }
        CP_COMMIT();
    };

    // ---------------- mainloop (first GEMM) ----------------
    load_stage(0, 0);
    if (NC > 1) load_stage(1, 1);
    for (int chnk = 0; chnk < NC; chnk++){
        int s = chnk % 3;
        if (chnk < NC-1) CP_WAIT1(); else CP_WAIT0();
        __syncthreads();
        if (chnk + 2 < NC) load_stage(chnk+2, (chnk+2)%3);
        compute_chunk_f<(MODE != 4)>(acc, sbase + (uint32_t)s*32768u,
                                     sbase + (uint32_t)s*32768u + 16384u, lane, wm, wn);
    }
    __syncthreads();   // all warps done with all stages before smem reuse

    // helper: write a split bf16 pair into the smem A2 image (64KB at offset 0)
    auto a2_put = [&](int rowl, int col, float v0, float v1){
        uint32_t hi, lo; split2(v0, v1, hi, lo);
        int kc = col >> 5, kl = col & 31, c = kl >> 3, by = (kl & 7)*2;
        char* base = smc + kc*16384 + rowl*128;
        *(uint32_t*)(base + (((c  )^(rowl&7))<<4) + by) = hi;
        *(uint32_t*)(base + (((c+4)^(rowl&7))<<4) + by) = lo;
    };

    if (MODE == 0){
        // phase 1: x2 = acc + bc + xc -> gmem fp32 + smem A2 split image
#pragma unroll
        for (int mf = 0; mf < 4; mf++)
#pragma unroll
            for (int half = 0; half < 2; half++){
                int rowl = wm*64 + mf*16 + half*8 + (lane>>2);
#pragma unroll
                for (int nf = 0; nf < 4; nf++){
                    int col = wn*32 + nf*8 + (lane&3)*2;
                    size_t off = (size_t)(m0 + rowl)*128 + col;
                    float2 xc = *(const float2*)&g_xc[off];
                    float o0 = acc[mf][nf][half*2+0] + g_bcp[col]   + xc.x;
                    float o1 = acc[mf][nf][half*2+1] + g_bcp[col+1] + xc.y;
                    float2 o = { o0, o1 };
                    *(float2*)&g_x2[off] = o;
                    a2_put(rowl, col, o0, o1);
                }
            }
#pragma unroll
        for (int i=0;i<4;i++)
#pragma unroll
            for (int j=0;j<4;j++)
#pragma unroll
                for (int q=0;q<4;q++) acc[i][j][q] = 0.f;
        __syncthreads();
        // phase 2: xeig = x2_tile @ E, double-buffered 16KB B steps
        loadB2(g_BEI, 4, 0, 0, 65536u);
        for (int kc = 0; kc < 4; kc++){
            CP_WAIT0(); __syncthreads();
            if (kc < 3) loadB2(g_BEI, 4, 0, kc+1, 65536u + (uint32_t)((kc+1)&1)*16384u);
            compute_chunk_f<true>(acc, sbase + (uint32_t)kc*16384u,
                                  sbase + 65536u + (uint32_t)(kc&1)*16384u, lane, wm, wn);
        }
        // epilogue: write xeig fp32 + column partials
#pragma unroll
        for (int mf = 0; mf < 4; mf++)
#pragma unroll
            for (int nf = 0; nf < 4; nf++){
                int row = m0 + wm*64 + mf*16 + (lane>>2);
                int col = wn*32 + nf*8 + (lane&3)*2;
#pragma unroll
                for (int half = 0; half < 2; half++){
                    size_t off = (size_t)(row + half*8)*128 + col;
                    float2 o = { acc[mf][nf][half*2+0], acc[mf][nf][half*2+1] };
                    *(float2*)&g_xeig[off] = o;
                }
            }
        __syncthreads();
        {
            float* ps = (float*)smc;
#pragma unroll
            for (int nf = 0; nf < 4; nf++)
#pragma unroll
                for (int j = 0; j < 2; j++){
                    float cs = 0.f;
#pragma unroll
                    for (int mf = 0; mf < 4; mf++)
#pragma unroll
                        for (int half = 0; half < 2; half++)
                            cs += acc[mf][nf][half*2+j];
                    cs += __shfl_xor_sync(0xffffffffu, cs, 4);
                    cs += __shfl_xor_sync(0xffffffffu, cs, 8);
                    cs += __shfl_xor_sync(0xffffffffu, cs, 16);
                    if ((lane >> 2) == 0)
                        ps[wm*128 + wn*32 + nf*8 + lane*2 + j] = cs;
                }
            __syncthreads();
            if (tid < 128)
                g_partial[(size_t)blockIdx.y*128 + tid] = ps[tid] + ps[128 + tid];
        }
    } else if (MODE == 2){
        // phase 1: LN stats over dec tile (partials in high smem region)
        float* prs = (float*)(smc + 65536);
        float* prq = prs + 512;
#pragma unroll
        for (int mf = 0; mf < 4; mf++)
#pragma unroll
            for (int half = 0; half < 2; half++){
                float s = 0.f, q = 0.f;
#pragma unroll
                for (int nf = 0; nf < 4; nf++)
#pragma unroll
                    for (int j = 0; j < 2; j++){
                        float v = acc[mf][nf][half*2+j];
                        s += v; q += v*v;
                    }
                s += __shfl_xor_sync(0xffffffffu, s, 1);
                s += __shfl_xor_sync(0xffffffffu, s, 2);
                q += __shfl_xor_sync(0xffffffffu, q, 1);
                q += __shfl_xor_sync(0xffffffffu, q, 2);
                if ((lane & 3) == 0){
                    int row = wm*64 + mf*16 + half*8 + (lane>>2);
                    prs[wn*128 + row] = s;
                    prq[wn*128 + row] = q;
                }
            }
        __syncthreads();
        // phase 2: out1 = x2 + dec ; dn -> smem A2 image
#pragma unroll
        for (int mf = 0; mf < 4; mf++)
#pragma unroll
            for (int half = 0; half < 2; half++){
                int rowl = wm*64 + mf*16 + half*8 + (lane>>2);
                float S = prs[rowl] + prs[128+rowl] + prs[256+rowl] + prs[384+rowl];
                float Q = prq[rowl] + prq[128+rowl] + prq[256+rowl] + prq[384+rowl];
                float mean = S*(1.f/128.f);
                float rstd = rsqrtf(Q*(1.f/128.f) - mean*mean + 1e-5f);
#pragma unroll
                for (int nf = 0; nf < 4; nf++){
                    int col = wn*32 + nf*8 + (lane&3)*2;
                    float v0 = acc[mf][nf][half*2+0];
                    float v1 = acc[mf][nf][half*2+1];
                    size_t off = (size_t)(m0 + rowl)*128 + col;
                    float2 x2v = *(const float2*)&g_x2[off];
                    float2 o1 = { x2v.x + v0, x2v.y + v1 };
                    *(float2*)&Cext[off] = o1;
                    float d0 = (v0 - mean)*rstd*g_gtp[col]   + g_btp[col];
                    float d1 = (v1 - mean)*rstd*g_gtp[col+1] + g_btp[col+1];
                    a2_put(rowl, col, d0, d1);
                }
            }
        __syncthreads();   // dn image complete; prs/prq region free for B stages
        // phase 3: h1 = gelu(dn @ W1 + b1), 16 double-buffered 16KB B steps
        loadB2(g_B1I, 4, 0, 0, 65536u);
        for (int s2 = 0; s2 < 16; s2++){
            int jn = s2 >> 2, kc = s2 & 3;
            if (kc == 0){
#pragma unroll
                for (int i=0;i<4;i++)
#pragma unroll
                    for (int j=0;j<4;j++)
#pragma unroll
                        for (int q=0;q<4;q++) acc[i][j][q] = 0.f;
            }
            CP_WAIT0(); __syncthreads();
            if (s2 < 15){
                int ns = s2 + 1;
                loadB2(g_B1I, 4, (ns>>2)*128, ns&3, 65536u + (uint32_t)(ns&1)*16384u);
            }
            compute_chunk_f<true>(acc, sbase + (uint32_t)kc*16384u,
                                  sbase + 65536u + (uint32_t)(s2&1)*16384u, lane, wm, wn);
            if (kc == 3){
                // epilogue: h1 tile (bf16-only plane)
#pragma unroll
                for (int mf = 0; mf < 4; mf++)
#pragma unroll
                    for (int nf = 0; nf < 4; nf++){
                        int row = m0 + wm*64 + mf*16 + (lane>>2);
                        int col = jn*128 + wn*32 + nf*8 + (lane&3)*2;
#pragma unroll
                        for (int half = 0; half < 2; half++){
                            float o0 = gelu_f(acc[mf][nf][half*2+0] + biasExt[col]);
                            float o1 = gelu_f(acc[mf][nf][half*2+1] + biasExt[col+1]);
                            __nv_bfloat162 p;
                            p.x = __float2bfloat16(o0); p.y = __float2bfloat16(o1);
                            *(uint32_t*)&g_h1b[(size_t)(row + half*8)*512 + col] = *(uint32_t*)&p;
                        }
                    }
            }
        }
    } else {   // MODE 4
#pragma unroll
        for (int mf = 0; mf < 4; mf++)
#pragma unroll
            for (int nf = 0; nf < 4; nf++){
                int row = m0 + wm*64 + mf*16 + (lane>>2);
                int col = wn*32 + nf*8 + (lane&3)*2;
#pragma unroll
                for (int half = 0; half < 2; half++){
                    size_t off = (size_t)(row + half*8)*128 + col;
                    float2 p = *(const float2*)&Cext[off];
                    float2 o = { p.x + acc[mf][nf][half*2+0] + g_b2p[col],
                                 p.y + acc[mf][nf][half*2+1] + g_b2p[col+1] };
                    *(float2*)&Cext[off] = o;
                }
            }
    }
}

// ---------------- finish spatial mean -------------------------------------------
__global__ void k_mean2()
{
    __shared__ float sb[4][128];
    int c = threadIdx.x & 127, g = threadIdx.x >> 7;
    int bt = blockIdx.x;
    float s = 0.f;
    for (int j = g; j < 32; j += 4) s += g_partial[(size_t)(bt*32+j)*128 + c];
    sb[g][c] = s;
    __syncthreads();
    if (g == 0)
        g_xmean[bt*128 + c] = (sb[0][c]+sb[1][c]+sb[2][c]+sb[3][c]) * (1.f/4096.f);
}

// ---------------- tiny sequential part ------------------------------------------
__global__ void k_seq(const float* __restrict__ flux_re, const float* __restrict__ flux_im,
                      const float* __restrict__ dt_seq, const float* __restrict__ lam_flux_raw,
                      const float* __restrict__ Wsrc_re, const float* __restrict__ Wsrc_im,
                      const float* __restrict__ w_gate, const float* __restrict__ b_gate,
                      const float* __restrict__ lam_re_raw, const float* __restrict__ lam_im,
                      float* __restrict__ out3, int write_out3)
{
    __shared__ float fre[2][16][64], fim[2][16][64];
    int b = threadIdx.x >> 6, d = threadIdx.x & 63;
    float lamf = softplus_f(lam_flux_raw[d]);
    float vr = flux_re[b*64+d], vi = flux_im[b*64+d];
    for (int t = 0; t < 16; t++){
        float dt = dt_seq[b*16+t];
        float Af = expf(-lamf*dt);
        int bt = b*16 + t;
        float xr = g_xmean[bt*128 + 2*d], xi = g_xmean[bt*128 + 2*d + 1];
        vr = Af*vr + xr*dt;
        vi = Af*vi + xi*dt;
        fre[b][t][d] = vr; fim[b][t][d] = vi;
    }
    __syncthreads();
    int e = d;
    float lr = -softplus_f(lam_re_raw[e]);
    float li = lam_im[e];
    float inv = 1.f/(lr*lr + li*li);
    float wg = w_gate[e], bg = b_gate[e];
    for (int t = 0; t < 16; t++){
        float sr = 0.f, si = 0.f;
        for (int dd = 0; dd < 64; dd++){
            float wr = Wsrc_re[dd*64+e], wi = Wsrc_im[dd*64+e];
            float fr = fre[b][t][dd], fi = fim[b][t][dd];
            sr += fr*wr - fi*wi;
            si += fr*wi + fi*wr;
        }
        float gate = 1.f/(1.f + expf(-(fre[b][t][e]*wg + bg)));
        float dt = dt_seq[b*16+t];
        float er = expf(lr*dt);
        float odr = er*cosf(li*dt), odi = er*sinf(li*dt);
        float nr = odr - 1.f, ni = odi;
        float ofr = (nr*lr + ni*li)*inv;
        float ofi = (ni*lr - nr*li)*inv;
        int idx = (b*16+t)*64 + e;
        g_od[2*idx] = odr;        g_od[2*idx+1] = odi;
        g_cA[2*idx] = gate*ofr;   g_cA[2*idx+1] = gate*ofi;
        float s1r = sr*(1.f-gate), s1i = si*(1.f-gate);
        g_cB[2*idx]   = s1r*ofr - s1i*ofi;
        g_cB[2*idx+1] = s1r*ofi + s1i*ofr;
    }
    if (write_out3){
        out3[(b*64+e)*2+0] = fre[b][15][e];
        out3[(b*64+e)*2+1] = fim[b][15][e];
    }
}

// ---------------- per-(b,h,w,e) recurrence; writes uout split planes ------------
__global__ void k_scan(const float* __restrict__ h_re, const float* __restrict__ h_im,
                       float* __restrict__ out2, int write_out2)
{
    int bh = blockIdx.x;
    int b = bh >> 6, h = bh & 63;
    int w = (blockIdx.y << 2) + (threadIdx.x >> 6);
    int e = threadIdx.x & 63;
    __shared__ float s_od[16][128], s_cA[16][128], s_cB[16][128];
    for (int i = threadIdx.x; i < 16*128; i += 256){
        int t = i>>7, c = i&127;
        s_od[t][c] = g_od[b*2048 + i];
        s_cA[t][c] = g_cA[b*2048 + i];
        s_cB[t][c] = g_cB[b*2048 + i];
    }
    __syncthreads();
    int hw = h*64 + w;
    size_t hidx = ((size_t)(b*64 + h)*64 + w)*64 + e;
    float vr = h_re[hidx], vi = h_im[hidx];
    for (int t = 0; t < 16; t++){
        size_t xoff = (((size_t)(b*16+t)*4096 + hw)*64 + e)*2;
        float xr = g_xeig[xoff], xi = g_xeig[xoff+1];
        float odr = s_od[t][2*e], odi = s_od[t][2*e+1];
        float car = s_cA[t][2*e], cai = s_cA[t][2*e+1];
        float cbr = s_cB[t][2*e], cbi = s_cB[t][2*e+1];
        float ur = xr*car - xi*cai + cbr;
        float ui = xr*cai + xi*car + cbi;
        float nvr = odr*vr - odi*vi + ur;
        float nvi = odr*vi + odi*vr + ui;
        vr = nvr; vi = nvi;
        uint32_t hi, lo; split2(vr, vi, hi, lo);
        *(uint32_t*)&g_uouth[xoff] = hi;
        *(uint32_t*)&g_uoutl[xoff] = lo;
    }
    if (write_out2){
        out2[hidx*2]   = vr;
        out2[hidx*2+1] = vi;
    }
}

// ---------------- launch ---------------------------------------------------------
extern "C" void kernel_launch(void* const* d_in, const int* in_sizes, int n_in,
                              void* d_out, int out_size)
{
    const float* x_re   = (const float*)d_in[0];
    const float* x_im   = (const float*)d_in[1];
    const float* h_re   = (const float*)d_in[2];
    const float* h_im   = (const float*)d_in[3];
    const float* flux_re= (const float*)d_in[4];
    const float* flux_im= (const float*)d_in[5];
    const float* dt_seq = (const float*)d_in[6];
    const float* g_s    = (const float*)d_in[7];
    const float* b_s    = (const float*)d_in[8];
    const float* Wc     = (const float*)d_in[9];
    const float* bc     = (const float*)d_in[10];
    const float* g_t    = (const float*)d_in[11];
    const float* b_t    = (const float*)d_in[12];
    const float* E_re   = (const float*)d_in[13];
    const float* E_im   = (const float*)d_in[14];
    const float* Dec_re = (const float*)d_in[15];
    const float* Dec_im = (const float*)d_in[16];
    const float* lam_flux_raw = (const float*)d_in[17];
    const float* Wsrc_re= (const float*)d_in[18];
    const float* Wsrc_im= (const float*)d_in[19];
    const float* w_gate = (const float*)d_in[20];
    const float* b_gate = (const float*)d_in[21];
    const float* lam_re_raw = (const float*)d_in[22];
    const float* lam_im = (const float*)d_in[23];
    const float* W1     = (const float*)d_in[24];
    const float* b1     = (const float*)d_in[25];
    const float* W2     = (const float*)d_in[26];
    const float* b2     = (const float*)d_in[27];

    float* out = (float*)d_out;
    const int Z_ELEMS  = 2*16*64*64*64*2;
    const int H_ELEMS  = 2*64*64*64*2;
    const int F_ELEMS  = 2*64*2;
    int full = (out_size >= Z_ELEMS + H_ELEMS + F_ELEMS) ? 1 : 0;
    float* out2 = out + Z_ELEMS;
    float* out3 = out + Z_ELEMS + H_ELEMS;

    const int SMEMSZ = 3*32768;
    cudaFuncSetAttribute(k_mma<0,1152,128>, cudaFuncAttributeMaxDynamicSharedMemorySize, SMEMSZ);
    cudaFuncSetAttribute(k_mma<2, 128,128>, cudaFuncAttributeMaxDynamicSharedMemorySize, SMEMSZ);
    cudaFuncSetAttribute(k_mma<4, 512,128>, cudaFuncAttributeMaxDynamicSharedMemorySize, SMEMSZ);

    k_prep<<<256,256>>>(Wc, bc, E_re, E_im, Dec_re, Dec_im, W1, W2, b2, g_t, b_t);
    k_ln<<<dim3(32,66),256>>>(x_re, x_im, g_s, b_s);
    k_mma<0,1152,128><<<dim3(1,1024),256,SMEMSZ>>>(nullptr, nullptr);  // conv -> x2 -> xeig
    k_mean2<<<32,512>>>();
    k_seq<<<1,128>>>(flux_re, flux_im, dt_seq, lam_flux_raw, Wsrc_re, Wsrc_im,
                     w_gate, b_gate, lam_re_raw, lam_im, out3, full);
    k_scan<<<dim3(128,16),256>>>(h_re, h_im, out2, full);
    k_mma<2, 128,128><<<dim3(1,1024),256,SMEMSZ>>>(out, b1);           // dec->out1/dn->h1
    k_mma<4, 512,128><<<dim3(1,1024),256,SMEMSZ>>>(out, nullptr);      // out += h1@W2 + b2
}